// round 1
// baseline (speedup 1.0000x reference)
#include <cuda_runtime.h>

#define S_LEN  1024
#define B_SZ   8
#define E_DIM  1024
#define H_NUM  16
#define D_HEAD 64
#define NB     (B_SZ * E_DIM)           /* 8192 = s-stride in [S,B,E] */
#define NBUF   (S_LEN * B_SZ * E_DIM)   /* 8M floats = 32 MB */

// Scratch (no allocations allowed) — 6 x 32MB
__device__ float g_a[NBUF];
__device__ float g_b[NBUF];
__device__ float g_c[NBUF];
__device__ float g_qp[NBUF];
__device__ float g_kp[NBUF];
__device__ float g_vp[NBUF];

// ---------------------------------------------------------------------------
// GEMM NT: C[m, n] = sum_k A_row(m)[k] * Bw[n*K + k]
// A row m lives at A + (m % P)*sa0 + (m / P)*sa1   (handles [B,S,x]<->[S,B,x])
// C is contiguous: row m at C + m*N.
// Tile 128x128x16, 256 threads, 8x8 per thread (split 4+4 for conflict-free LDS.128)
// ---------------------------------------------------------------------------
__global__ __launch_bounds__(256) void gemm_nt(
    const float* __restrict__ A, const float* __restrict__ Bw,
    float* __restrict__ C, int K, int N, int P, int sa0, int sa1)
{
    __shared__ float As[16][132];
    __shared__ float Bs[16][132];

    const int tid  = threadIdx.x;
    const int ty   = tid >> 4;          // 0..15
    const int tx   = tid & 15;          // 0..15
    const int m_blk = blockIdx.y << 7;
    const int n_blk = blockIdx.x << 7;
    const int lr = tid >> 2;            // 0..63
    const int lc = (tid & 3) << 2;      // {0,4,8,12}

    const int am0 = m_blk + lr;
    const int am1 = am0 + 64;
    const float* a0p = A + (size_t)(am0 % P) * sa0 + (size_t)(am0 / P) * sa1 + lc;
    const float* a1p = A + (size_t)(am1 % P) * sa0 + (size_t)(am1 / P) * sa1 + lc;
    const float* b0p = Bw + (size_t)(n_blk + lr) * K + lc;
    const float* b1p = Bw + (size_t)(n_blk + lr + 64) * K + lc;

    float acc[8][8];
#pragma unroll
    for (int i = 0; i < 8; i++)
#pragma unroll
        for (int j = 0; j < 8; j++) acc[i][j] = 0.f;

    for (int k0 = 0; k0 < K; k0 += 16) {
        float4 a0 = *(const float4*)(a0p + k0);
        float4 a1 = *(const float4*)(a1p + k0);
        float4 b0 = *(const float4*)(b0p + k0);
        float4 b1 = *(const float4*)(b1p + k0);
        __syncthreads();
        As[lc+0][lr] = a0.x; As[lc+1][lr] = a0.y; As[lc+2][lr] = a0.z; As[lc+3][lr] = a0.w;
        As[lc+0][lr+64] = a1.x; As[lc+1][lr+64] = a1.y; As[lc+2][lr+64] = a1.z; As[lc+3][lr+64] = a1.w;
        Bs[lc+0][lr] = b0.x; Bs[lc+1][lr] = b0.y; Bs[lc+2][lr] = b0.z; Bs[lc+3][lr] = b0.w;
        Bs[lc+0][lr+64] = b1.x; Bs[lc+1][lr+64] = b1.y; Bs[lc+2][lr+64] = b1.z; Bs[lc+3][lr+64] = b1.w;
        __syncthreads();
#pragma unroll
        for (int k = 0; k < 16; k++) {
            float a[8], b[8];
            *(float4*)&a[0] = *(const float4*)&As[k][ty*4];
            *(float4*)&a[4] = *(const float4*)&As[k][64 + ty*4];
            *(float4*)&b[0] = *(const float4*)&Bs[k][tx*4];
            *(float4*)&b[4] = *(const float4*)&Bs[k][64 + tx*4];
#pragma unroll
            for (int i = 0; i < 8; i++)
#pragma unroll
                for (int j = 0; j < 8; j++)
                    acc[i][j] = fmaf(a[i], b[j], acc[i][j]);
        }
    }

#pragma unroll
    for (int ih = 0; ih < 2; ih++)
#pragma unroll
        for (int ii = 0; ii < 4; ii++) {
            const int m = m_blk + ih*64 + ty*4 + ii;
            float* cp = C + (size_t)m * N + n_blk;
            float4 v0 = make_float4(acc[ih*4+ii][0], acc[ih*4+ii][1],
                                    acc[ih*4+ii][2], acc[ih*4+ii][3]);
            float4 v1 = make_float4(acc[ih*4+ii][4], acc[ih*4+ii][5],
                                    acc[ih*4+ii][6], acc[ih*4+ii][7]);
            *(float4*)(cp + tx*4)      = v0;
            *(float4*)(cp + 64 + tx*4) = v1;
        }
}

// ---------------------------------------------------------------------------
// RoPE, position index = batch b (per reference!). In-place on q and k [S,B,E].
// One thread handles pair (j, j+32) inside a head.
// ---------------------------------------------------------------------------
__global__ __launch_bounds__(256) void rope_kernel(float* __restrict__ q,
                                                   float* __restrict__ k)
{
    const int idx = blockIdx.x * 256 + threadIdx.x;     // S*B*H*32 threads exactly
    const int j  = idx & 31;
    const int h  = (idx >> 5) & (H_NUM - 1);
    const int sb = idx >> 9;                            // s*B + b
    const int b  = sb & (B_SZ - 1);
    const size_t base = (size_t)sb * E_DIM + h * D_HEAD;
    // inv_freq = 10000^(-j/32)
    const float inv = expf((float)j * (-0.28782313662425575f)); // ln(1e4)/32
    const float ang = (float)b * inv;
    const float c = cosf(ang), s = sinf(ang);
    float x1 = q[base + j], x2 = q[base + j + 32];
    q[base + j]      = x1 * c - x2 * s;
    q[base + j + 32] = x2 * c + x1 * s;
    x1 = k[base + j]; x2 = k[base + j + 32];
    k[base + j]      = x1 * c - x2 * s;
    k[base + j + 32] = x2 * c + x1 * s;
}

// ---------------------------------------------------------------------------
// Fused flash attention (non-causal, online softmax), fp32.
// Grid: (S/64, B*H). Block: 256 threads (16x16), 4x4 register tile.
// qp/kp/vp/out are [S,B,H,D] flattened (s-stride NB).
// ---------------------------------------------------------------------------
#define ATTN_SMEM ((64*64 + 64*65 + 64*64 + 64*64) * 4)

__global__ __launch_bounds__(256) void attn_kernel(
    const float* __restrict__ qp, const float* __restrict__ kp,
    const float* __restrict__ vp, float* __restrict__ out)
{
    extern __shared__ float sm[];
    float* Qs = sm;                 // [64][64]
    float* Ks = Qs + 64*64;         // [64][65] (pad kills column-read conflicts)
    float* Vs = Ks + 64*65;         // [64][64]
    float* Ps = Vs + 64*64;         // [64][64]

    const int tid = threadIdx.x;
    const int ty  = tid >> 4, tx = tid & 15;
    const int b   = blockIdx.y >> 4;
    const int h   = blockIdx.y & 15;
    const int m0  = blockIdx.x << 6;

    const float* qb = qp + b*E_DIM + h*D_HEAD;
    const float* kb = kp + b*E_DIM + h*D_HEAD;
    const float* vb = vp + b*E_DIM + h*D_HEAD;

    for (int i = tid; i < 64*16; i += 256) {
        const int r = i >> 4, c4 = (i & 15) << 2;
        float4 v4 = *(const float4*)(qb + (size_t)(m0 + r) * NB + c4);
        *(float4*)&Qs[r*64 + c4] = v4;
    }

    float acc[4][4], run_m[4], run_l[4];
#pragma unroll
    for (int i = 0; i < 4; i++) {
        run_m[i] = -1e30f; run_l[i] = 0.f;
#pragma unroll
        for (int j = 0; j < 4; j++) acc[i][j] = 0.f;
    }

    for (int t0 = 0; t0 < S_LEN; t0 += 64) {
        __syncthreads();   // protect Ks/Vs/Ps readers of previous iter
        for (int i = tid; i < 64*16; i += 256) {
            const int r = i >> 4, c4 = (i & 15) << 2;
            float4 kv = *(const float4*)(kb + (size_t)(t0 + r) * NB + c4);
            Ks[r*65 + c4 + 0] = kv.x;
            Ks[r*65 + c4 + 1] = kv.y;
            Ks[r*65 + c4 + 2] = kv.z;
            Ks[r*65 + c4 + 3] = kv.w;
            float4 vv = *(const float4*)(vb + (size_t)(t0 + r) * NB + c4);
            *(float4*)&Vs[r*64 + c4] = vv;
        }
        __syncthreads();

        float sreg[4][4];
#pragma unroll
        for (int i = 0; i < 4; i++)
#pragma unroll
            for (int j = 0; j < 4; j++) sreg[i][j] = 0.f;

#pragma unroll 8
        for (int k = 0; k < 64; k++) {
            float qv[4], kv[4];
#pragma unroll
            for (int i = 0; i < 4; i++) qv[i] = Qs[(ty*4+i)*64 + k];   // bcast
#pragma unroll
            for (int j = 0; j < 4; j++) kv[j] = Ks[(tx*4+j)*65 + k];   // 2-way
#pragma unroll
            for (int i = 0; i < 4; i++)
#pragma unroll
                for (int j = 0; j < 4; j++)
                    sreg[i][j] = fmaf(qv[i], kv[j], sreg[i][j]);
        }

#pragma unroll
        for (int i = 0; i < 4; i++) {
            float mx = run_m[i];
#pragma unroll
            for (int j = 0; j < 4; j++) {
                sreg[i][j] *= 0.125f;                 // 1/sqrt(64)
                mx = fmaxf(mx, sreg[i][j]);
            }
#pragma unroll
            for (int off = 8; off > 0; off >>= 1)
                mx = fmaxf(mx, __shfl_xor_sync(0xffffffffu, mx, off, 16));
            const float f = __expf(run_m[i] - mx);
            float rs = 0.f;
#pragma unroll
            for (int j = 0; j < 4; j++) {
                const float p = __expf(sreg[i][j] - mx);
                sreg[i][j] = p;
                rs += p;
            }
#pragma unroll
            for (int off = 8; off > 0; off >>= 1)
                rs += __shfl_xor_sync(0xffffffffu, rs, off, 16);
            run_l[i] = run_l[i] * f + rs;
            run_m[i] = mx;
#pragma unroll
            for (int j = 0; j < 4; j++) acc[i][j] *= f;
        }

#pragma unroll
        for (int i = 0; i < 4; i++)
            *(float4*)&Ps[(ty*4+i)*64 + tx*4] =
                make_float4(sreg[i][0], sreg[i][1], sreg[i][2], sreg[i][3]);
        __syncthreads();

#pragma unroll 8
        for (int n = 0; n < 64; n++) {
            float pv[4];
#pragma unroll
            for (int i = 0; i < 4; i++) pv[i] = Ps[(ty*4+i)*64 + n];   // bcast
            const float4 vv = *(const float4*)&Vs[n*64 + tx*4];        // clean
#pragma unroll
            for (int i = 0; i < 4; i++) {
                acc[i][0] = fmaf(pv[i], vv.x, acc[i][0]);
                acc[i][1] = fmaf(pv[i], vv.y, acc[i][1]);
                acc[i][2] = fmaf(pv[i], vv.z, acc[i][2]);
                acc[i][3] = fmaf(pv[i], vv.w, acc[i][3]);
            }
        }
    }

#pragma unroll
    for (int i = 0; i < 4; i++) {
        const float inv = 1.0f / run_l[i];
        const int m = m0 + ty*4 + i;
        float4 o = make_float4(acc[i][0]*inv, acc[i][1]*inv,
                               acc[i][2]*inv, acc[i][3]*inv);
        *(float4*)(out + (size_t)m * NB + b*E_DIM + h*D_HEAD + tx*4) = o;
    }
}

// ---------------------------------------------------------------------------
// x = query + ob ; LayerNorm(last dim) * gamma + beta.  One block per row.
// ---------------------------------------------------------------------------
__global__ __launch_bounds__(256) void addln_kernel(
    const float* __restrict__ qin, const float* __restrict__ ob,
    const float* __restrict__ gamma, const float* __restrict__ beta,
    float* __restrict__ out)
{
    const int row = blockIdx.x;
    const int tid = threadIdx.x;
    const size_t base = (size_t)row * E_DIM;

    const float4 a = *(const float4*)(qin + base + tid*4);
    const float4 c = *(const float4*)(ob  + base + tid*4);
    const float e0 = a.x + c.x, e1 = a.y + c.y, e2 = a.z + c.z, e3 = a.w + c.w;
    float s  = e0 + e1 + e2 + e3;
    float ss = e0*e0 + e1*e1 + e2*e2 + e3*e3;
#pragma unroll
    for (int off = 16; off > 0; off >>= 1) {
        s  += __shfl_xor_sync(0xffffffffu, s,  off);
        ss += __shfl_xor_sync(0xffffffffu, ss, off);
    }
    __shared__ float sw[8], ssw[8], red[2];
    const int wid = tid >> 5, lane = tid & 31;
    if (lane == 0) { sw[wid] = s; ssw[wid] = ss; }
    __syncthreads();
    if (tid == 0) {
        float S2 = 0.f, SS = 0.f;
        for (int i = 0; i < 8; i++) { S2 += sw[i]; SS += ssw[i]; }
        red[0] = S2; red[1] = SS;
    }
    __syncthreads();
    const float mu  = red[0] * (1.0f / E_DIM);
    const float var = red[1] * (1.0f / E_DIM) - mu * mu;
    const float r   = rsqrtf(var + 1e-5f);
    const float4 g  = *(const float4*)(gamma + tid*4);
    const float4 bt = *(const float4*)(beta  + tid*4);
    float4 o;
    o.x = (e0 - mu) * r * g.x + bt.x;
    o.y = (e1 - mu) * r * g.y + bt.y;
    o.z = (e2 - mu) * r * g.z + bt.z;
    o.w = (e3 - mu) * r * g.w + bt.w;
    *(float4*)(out + base + tid*4) = o;
}

// ---------------------------------------------------------------------------
extern "C" void kernel_launch(void* const* d_in, const int* in_sizes, int n_in,
                              void* d_out, int out_size)
{
    const float* query    = (const float*)d_in[0];
    const float* key      = (const float*)d_in[1];
    const float* value    = (const float*)d_in[2];
    const float* Wq       = (const float*)d_in[3];
    const float* Wk       = (const float*)d_in[4];
    const float* Wv       = (const float*)d_in[5];
    const float* in_proj  = (const float*)d_in[6];
    const float* out_proj = (const float*)d_in[7];
    const float* proj     = (const float*)d_in[8];
    const float* gamma    = (const float*)d_in[9];
    const float* beta     = (const float*)d_in[10];
    float* out = (float*)d_out;

    float *pa, *pb, *pc, *pqp, *pkp, *pvp;
    cudaGetSymbolAddress((void**)&pa,  g_a);
    cudaGetSymbolAddress((void**)&pb,  g_b);
    cudaGetSymbolAddress((void**)&pc,  g_c);
    cudaGetSymbolAddress((void**)&pqp, g_qp);
    cudaGetSymbolAddress((void**)&pkp, g_kp);
    cudaGetSymbolAddress((void**)&pvp, g_vp);

    cudaFuncSetAttribute(attn_kernel,
                         cudaFuncAttributeMaxDynamicSharedMemorySize, ATTN_SMEM);

    const dim3 gg(E_DIM / 128, (S_LEN * B_SZ) / 128);   // (8, 64)

    // q,k,v = swap(query/key/value) @ W{q,k,v}.T  -> [S,B,E]
    // A row m=s*B+b at (m%8)*S*O + (m/8)*O
    gemm_nt<<<gg, 256>>>(query, Wq, pa, 1024, 1024, B_SZ, S_LEN * E_DIM, E_DIM);
    gemm_nt<<<gg, 256>>>(key,   Wk, pb, 1024, 1024, B_SZ, S_LEN * E_DIM, E_DIM);
    gemm_nt<<<gg, 256>>>(value, Wv, pc, 1024, 1024, B_SZ, S_LEN * E_DIM, E_DIM);

    // RoPE in-place on q (pa) and k (pb); position index = b
    rope_kernel<<<(S_LEN * B_SZ * H_NUM * 32) / 256, 256>>>(pa, pb);

    // in_proj splits: qp/kp/vp -> [S,B,E] (contiguous A: P=1, sa1=K)
    gemm_nt<<<gg, 256>>>(pa, in_proj,                   pqp, 1024, 1024, 1, 0, 1024);
    gemm_nt<<<gg, 256>>>(pb, in_proj + E_DIM * E_DIM,   pkp, 1024, 1024, 1, 0, 1024);
    gemm_nt<<<gg, 256>>>(pc, in_proj + 2 * E_DIM * E_DIM, pvp, 1024, 1024, 1, 0, 1024);

    // attention -> pa  [S,B,E]
    const dim3 ga(S_LEN / 64, B_SZ * H_NUM);            // (16, 128)
    attn_kernel<<<ga, 256, ATTN_SMEM>>>(pqp, pkp, pvp, pa);

    // out_proj: pa @ out_proj.T -> pb [S,B,E]
    gemm_nt<<<gg, 256>>>(pa, out_proj, pb, 1024, 1024, 1, 0, 1024);

    // final proj with [S,B,E] -> [B,S,E] gather: m=b*S+s, row at (m%S)*NB + (m/S)*E
    gemm_nt<<<gg, 256>>>(pb, proj, pc, 1024, 1024, S_LEN, NB, E_DIM);

    // residual + layernorm -> out [B,S,O]
    addln_kernel<<<B_SZ * S_LEN, 256>>>(query, pc, gamma, beta, out);
}

// round 3
// speedup vs baseline: 2.6348x; 2.6348x over previous
#include <cuda_runtime.h>
#include <cuda_bf16.h>
#include <cstdint>

#define S_LEN  1024
#define B_SZ   8
#define E_DIM  1024
#define H_NUM  16
#define D_HEAD 64
#define NB     (B_SZ * E_DIM)           /* 8192 = s-stride in [S,B,E] */
#define NBUF   (S_LEN * B_SZ * E_DIM)   /* 8M floats = 32 MB */

// Scratch (no allocations allowed)
__device__ float g_a[NBUF];
__device__ float g_b[NBUF];
__device__ float g_c[NBUF];
__device__ float g_qp[NBUF];
__device__ float g_kp[NBUF];
__device__ float g_vp[NBUF];
__device__ __nv_bfloat16 g_wbf[8u * 1024u * 1024u];   // bf16 weights, 8 x 1M

// ===========================================================================
// Family-portable PTX helpers (NO tcgen05 — harness compiles compute_103)
// ===========================================================================
__device__ __forceinline__ uint32_t smem_u32(const void* p) {
    uint32_t a;
    asm("{ .reg .u64 t; cvta.to.shared.u64 t, %1; cvt.u32.u64 %0, t; }"
        : "=r"(a) : "l"(p));
    return a;
}

#define LDSM_X4(d, addr)                                                        \
    asm volatile("ldmatrix.sync.aligned.m8n8.x4.shared.b16 {%0,%1,%2,%3}, [%4];"\
        : "=r"((d)[0]), "=r"((d)[1]), "=r"((d)[2]), "=r"((d)[3]) : "r"(addr))

#define MMA_BF16(ac, a, b0, b1)                                                 \
    asm volatile("mma.sync.aligned.m16n8k16.row.col.f32.bf16.bf16.f32 "         \
        "{%0,%1,%2,%3}, {%4,%5,%6,%7}, {%8,%9}, {%0,%1,%2,%3};"                 \
        : "+f"((ac)[0]), "+f"((ac)[1]), "+f"((ac)[2]), "+f"((ac)[3])            \
        : "r"((a)[0]), "r"((a)[1]), "r"((a)[2]), "r"((a)[3]),                   \
          "r"(b0), "r"(b1))

#define CP_ASYNC16(s, g)                                                        \
    asm volatile("cp.async.cg.shared.global [%0], [%1], 16;" :: "r"(s), "l"(g))
#define CP_COMMIT() asm volatile("cp.async.commit_group;" ::: "memory")
#define CP_WAIT0()  asm volatile("cp.async.wait_group 0;" ::: "memory")

__device__ __forceinline__ void sts_bf16x8(uint32_t addr, float4 lo, float4 hi) {
    __nv_bfloat162 p0 = __floats2bfloat162_rn(lo.x, lo.y);
    __nv_bfloat162 p1 = __floats2bfloat162_rn(lo.z, lo.w);
    __nv_bfloat162 p2 = __floats2bfloat162_rn(hi.x, hi.y);
    __nv_bfloat162 p3 = __floats2bfloat162_rn(hi.z, hi.w);
    asm volatile("st.shared.v4.b32 [%0], {%1,%2,%3,%4};"
        :: "r"(addr),
           "r"(*reinterpret_cast<uint32_t*>(&p0)),
           "r"(*reinterpret_cast<uint32_t*>(&p1)),
           "r"(*reinterpret_cast<uint32_t*>(&p2)),
           "r"(*reinterpret_cast<uint32_t*>(&p3)));
}

// ===========================================================================
// bf16 mma.sync GEMM: C[m, n] = sum_k A_row(m)[k] * Bw[n*1024 + k]
// A fp32 (reg-converted), Bw bf16. M=8192, N=1024, K=1024.
// CTA 128x128, K-chunk 32, double buffer, 8 warps, warp tile 32x64.
// Padded smem rows: 32 + 8 bf16 = 80 B (conflict-free ldmatrix).
// A row m at A + (m % P)*sa0 + (m / P)*sa1.
// ===========================================================================
#define TSTRIDE 40            /* bf16 elements per padded row */
#define TBYTES  (128 * TSTRIDE * 2)   /* 10240 bytes per tile buffer */

__global__ __launch_bounds__(256, 2) void gemm_mma(
    const float* __restrict__ A, const __nv_bfloat16* __restrict__ Bw,
    float* __restrict__ C, int P, int sa0, int sa1)
{
    __shared__ __align__(16) __nv_bfloat16 As[2][128 * TSTRIDE];
    __shared__ __align__(16) __nv_bfloat16 Bs[2][128 * TSTRIDE];

    const int tid  = threadIdx.x;
    const int lane = tid & 31;
    const int w    = tid >> 5;
    const int wm   = w >> 1;          // 0..3  (m-warp)
    const int wn   = w & 1;           // 0..1  (n-warp)
    const int m_blk = blockIdx.y << 7;
    const int n_blk = blockIdx.x << 7;

    // ---- load assignments: 16B chunks; rows r0 and r0+64 per thread ----
    const int r0 = tid >> 2;          // 0..63
    const int q8 = (tid & 3) << 3;    // col {0,8,16,24}

    const int am0 = m_blk + r0, am1 = am0 + 64;
    const float* ap0 = A + (size_t)(am0 % P) * sa0 + (size_t)(am0 / P) * sa1 + q8;
    const float* ap1 = A + (size_t)(am1 % P) * sa0 + (size_t)(am1 / P) * sa1 + q8;
    const __nv_bfloat16* bp0 = Bw + (size_t)(n_blk + r0) * 1024 + q8;
    const __nv_bfloat16* bp1 = Bw + (size_t)(n_blk + r0 + 64) * 1024 + q8;

    const uint32_t sa = smem_u32(As);
    const uint32_t sb = smem_u32(Bs);
    const uint32_t a_sts0 = sa + (uint32_t)(r0 * TSTRIDE + q8) * 2;
    const uint32_t a_sts1 = sa + (uint32_t)((r0 + 64) * TSTRIDE + q8) * 2;
    const uint32_t b_sts0 = sb + (uint32_t)(r0 * TSTRIDE + q8) * 2;
    const uint32_t b_sts1 = sb + (uint32_t)((r0 + 64) * TSTRIDE + q8) * 2;

    // ---- ldmatrix lane bases (byte offsets within a buffer) ----
    // A: row = wm*32 + mt*16 + (l&15), col = ks*16 + (l>>4)*8
    const uint32_t a_lm = sa +
        (uint32_t)((wm * 32 + (lane & 15)) * TSTRIDE) * 2 + ((lane >> 4) << 4);
    // B: n = wn*64 + bt*16 + ((l>>4)&1)*8 + (l&7), k = ks*16 + ((l>>3)&1)*8
    const uint32_t b_lm = sb +
        (uint32_t)((wn * 64 + (((lane >> 4) & 1) << 3) + (lane & 7)) * TSTRIDE) * 2
        + (((lane >> 3) & 1) << 4);

    float acc[2][8][4];
#pragma unroll
    for (int mt = 0; mt < 2; mt++)
#pragma unroll
        for (int nt = 0; nt < 8; nt++)
#pragma unroll
            for (int j = 0; j < 4; j++) acc[mt][nt][j] = 0.f;

    // ---- prologue: chunk 0 ----
    float4 na00 = *(const float4*)(ap0);
    float4 na01 = *(const float4*)(ap0 + 4);
    float4 na10 = *(const float4*)(ap1);
    float4 na11 = *(const float4*)(ap1 + 4);
    CP_ASYNC16(b_sts0, bp0);
    CP_ASYNC16(b_sts1, bp1);
    CP_COMMIT();
    sts_bf16x8(a_sts0, na00, na01);
    sts_bf16x8(a_sts1, na10, na11);
    CP_WAIT0();
    __syncthreads();

    for (int i = 0; i < 32; i++) {
        const int p = i & 1, q = p ^ 1;
        if (i < 31) {
            const int ko = (i + 1) << 5;
            na00 = *(const float4*)(ap0 + ko);
            na01 = *(const float4*)(ap0 + ko + 4);
            na10 = *(const float4*)(ap1 + ko);
            na11 = *(const float4*)(ap1 + ko + 4);
            CP_ASYNC16(b_sts0 + q * TBYTES, bp0 + ko);
            CP_ASYNC16(b_sts1 + q * TBYTES, bp1 + ko);
            CP_COMMIT();
        }

        // ---- compute on buffer p ----
        const uint32_t ab = a_lm + p * TBYTES;
        const uint32_t bb = b_lm + p * TBYTES;
#pragma unroll
        for (int ks = 0; ks < 2; ks++) {
            uint32_t af0[4], af1[4];
            LDSM_X4(af0, ab + ks * 32);
            LDSM_X4(af1, ab + ks * 32 + 16 * TSTRIDE * 2);
            uint32_t bf[4][4];
#pragma unroll
            for (int bt = 0; bt < 4; bt++)
                LDSM_X4(bf[bt], bb + ks * 32 + bt * 16 * TSTRIDE * 2);
#pragma unroll
            for (int nt = 0; nt < 8; nt++) {
                const uint32_t bb0 = (nt & 1) ? bf[nt >> 1][2] : bf[nt >> 1][0];
                const uint32_t bb1 = (nt & 1) ? bf[nt >> 1][3] : bf[nt >> 1][1];
                MMA_BF16(acc[0][nt], af0, bb0, bb1);
                MMA_BF16(acc[1][nt], af1, bb0, bb1);
            }
        }

        if (i < 31) {
            sts_bf16x8(a_sts0 + q * TBYTES, na00, na01);
            sts_bf16x8(a_sts1 + q * TBYTES, na10, na11);
            CP_WAIT0();
        }
        __syncthreads();
    }

    // ---- epilogue: fp32 accum -> C ----
    const int crow = m_blk + wm * 32 + (lane >> 2);
    const int ccol = n_blk + wn * 64 + ((lane & 3) << 1);
#pragma unroll
    for (int mt = 0; mt < 2; mt++)
#pragma unroll
        for (int nt = 0; nt < 8; nt++) {
            float* cp = C + (size_t)(crow + mt * 16) * 1024 + ccol + nt * 8;
            *(float2*)cp = make_float2(acc[mt][nt][0], acc[mt][nt][1]);
            *(float2*)(cp + 8 * 1024) = make_float2(acc[mt][nt][2], acc[mt][nt][3]);
        }
}

// ===========================================================================
// Weight fp32 -> bf16 convert: 8M elements into g_wbf
// [Wq | Wk | Wv | in_q | in_k | in_v | out_proj | proj], 1M each
// ===========================================================================
__global__ __launch_bounds__(256) void convw_kernel(
    const float* __restrict__ Wq, const float* __restrict__ Wk,
    const float* __restrict__ Wv, const float* __restrict__ inp,
    const float* __restrict__ outp, const float* __restrict__ projw,
    __nv_bfloat16* __restrict__ dst)
{
    const int idx = blockIdx.x * 256 + threadIdx.x;
    const size_t e = (size_t)idx << 2;
    const int seg = (int)(e >> 20);
    const size_t off = e & 0xFFFFFu;
    const float* src;
    switch (seg) {
        case 0: src = Wq; break;
        case 1: src = Wk; break;
        case 2: src = Wv; break;
        case 3: case 4: case 5: src = inp + ((size_t)(seg - 3) << 20); break;
        case 6: src = outp; break;
        default: src = projw; break;
    }
    const float4 v = *(const float4*)(src + off);
    __nv_bfloat162 lo = __floats2bfloat162_rn(v.x, v.y);
    __nv_bfloat162 hi = __floats2bfloat162_rn(v.z, v.w);
    uint2 pv;
    pv.x = *reinterpret_cast<uint32_t*>(&lo);
    pv.y = *reinterpret_cast<uint32_t*>(&hi);
    *reinterpret_cast<uint2*>(dst + e) = pv;
}

// ---------------------------------------------------------------------------
// RoPE, position index = batch b (per reference!). In-place on q and k [S,B,E].
// ---------------------------------------------------------------------------
__global__ __launch_bounds__(256) void rope_kernel(float* __restrict__ q,
                                                   float* __restrict__ k)
{
    const int idx = blockIdx.x * 256 + threadIdx.x;
    const int j  = idx & 31;
    const int h  = (idx >> 5) & (H_NUM - 1);
    const int sb = idx >> 9;
    const int b  = sb & (B_SZ - 1);
    const size_t base = (size_t)sb * E_DIM + h * D_HEAD;
    const float inv = expf((float)j * (-0.28782313662425575f)); // ln(1e4)/32
    const float ang = (float)b * inv;
    const float c = cosf(ang), s = sinf(ang);
    float x1 = q[base + j], x2 = q[base + j + 32];
    q[base + j]      = x1 * c - x2 * s;
    q[base + j + 32] = x2 * c + x1 * s;
    x1 = k[base + j]; x2 = k[base + j + 32];
    k[base + j]      = x1 * c - x2 * s;
    k[base + j + 32] = x2 * c + x1 * s;
}

// ---------------------------------------------------------------------------
// Fused flash attention (non-causal, online softmax), fp32.
// ---------------------------------------------------------------------------
#define ATTN_SMEM ((64*64 + 64*65 + 64*64 + 64*64) * 4)

__global__ __launch_bounds__(256) void attn_kernel(
    const float* __restrict__ qp, const float* __restrict__ kp,
    const float* __restrict__ vp, float* __restrict__ out)
{
    extern __shared__ float sm[];
    float* Qs = sm;
    float* Ks = Qs + 64*64;
    float* Vs = Ks + 64*65;
    float* Ps = Vs + 64*64;

    const int tid = threadIdx.x;
    const int ty  = tid >> 4, tx = tid & 15;
    const int b   = blockIdx.y >> 4;
    const int h   = blockIdx.y & 15;
    const int m0  = blockIdx.x << 6;

    const float* qb = qp + b*E_DIM + h*D_HEAD;
    const float* kb = kp + b*E_DIM + h*D_HEAD;
    const float* vb = vp + b*E_DIM + h*D_HEAD;

    for (int i = tid; i < 64*16; i += 256) {
        const int r = i >> 4, c4 = (i & 15) << 2;
        float4 v4 = *(const float4*)(qb + (size_t)(m0 + r) * NB + c4);
        *(float4*)&Qs[r*64 + c4] = v4;
    }

    float acc[4][4], run_m[4], run_l[4];
#pragma unroll
    for (int i = 0; i < 4; i++) {
        run_m[i] = -1e30f; run_l[i] = 0.f;
#pragma unroll
        for (int j = 0; j < 4; j++) acc[i][j] = 0.f;
    }

    for (int t0 = 0; t0 < S_LEN; t0 += 64) {
        __syncthreads();
        for (int i = tid; i < 64*16; i += 256) {
            const int r = i >> 4, c4 = (i & 15) << 2;
            float4 kv = *(const float4*)(kb + (size_t)(t0 + r) * NB + c4);
            Ks[r*65 + c4 + 0] = kv.x;
            Ks[r*65 + c4 + 1] = kv.y;
            Ks[r*65 + c4 + 2] = kv.z;
            Ks[r*65 + c4 + 3] = kv.w;
            float4 vv = *(const float4*)(vb + (size_t)(t0 + r) * NB + c4);
            *(float4*)&Vs[r*64 + c4] = vv;
        }
        __syncthreads();

        float sreg[4][4];
#pragma unroll
        for (int i = 0; i < 4; i++)
#pragma unroll
            for (int j = 0; j < 4; j++) sreg[i][j] = 0.f;

#pragma unroll 8
        for (int k = 0; k < 64; k++) {
            float qv[4], kv[4];
#pragma unroll
            for (int i = 0; i < 4; i++) qv[i] = Qs[(ty*4+i)*64 + k];
#pragma unroll
            for (int j = 0; j < 4; j++) kv[j] = Ks[(tx*4+j)*65 + k];
#pragma unroll
            for (int i = 0; i < 4; i++)
#pragma unroll
                for (int j = 0; j < 4; j++)
                    sreg[i][j] = fmaf(qv[i], kv[j], sreg[i][j]);
        }

#pragma unroll
        for (int i = 0; i < 4; i++) {
            float mx = run_m[i];
#pragma unroll
            for (int j = 0; j < 4; j++) {
                sreg[i][j] *= 0.125f;
                mx = fmaxf(mx, sreg[i][j]);
            }
#pragma unroll
            for (int off = 8; off > 0; off >>= 1)
                mx = fmaxf(mx, __shfl_xor_sync(0xffffffffu, mx, off, 16));
            const float f = __expf(run_m[i] - mx);
            float rs = 0.f;
#pragma unroll
            for (int j = 0; j < 4; j++) {
                const float p = __expf(sreg[i][j] - mx);
                sreg[i][j] = p;
                rs += p;
            }
#pragma unroll
            for (int off = 8; off > 0; off >>= 1)
                rs += __shfl_xor_sync(0xffffffffu, rs, off, 16);
            run_l[i] = run_l[i] * f + rs;
            run_m[i] = mx;
#pragma unroll
            for (int j = 0; j < 4; j++) acc[i][j] *= f;
        }

#pragma unroll
        for (int i = 0; i < 4; i++)
            *(float4*)&Ps[(ty*4+i)*64 + tx*4] =
                make_float4(sreg[i][0], sreg[i][1], sreg[i][2], sreg[i][3]);
        __syncthreads();

#pragma unroll 8
        for (int n = 0; n < 64; n++) {
            float pv[4];
#pragma unroll
            for (int i = 0; i < 4; i++) pv[i] = Ps[(ty*4+i)*64 + n];
            const float4 vv = *(const float4*)&Vs[n*64 + tx*4];
#pragma unroll
            for (int i = 0; i < 4; i++) {
                acc[i][0] = fmaf(pv[i], vv.x, acc[i][0]);
                acc[i][1] = fmaf(pv[i], vv.y, acc[i][1]);
                acc[i][2] = fmaf(pv[i], vv.z, acc[i][2]);
                acc[i][3] = fmaf(pv[i], vv.w, acc[i][3]);
            }
        }
    }

#pragma unroll
    for (int i = 0; i < 4; i++) {
        const float inv = 1.0f / run_l[i];
        const int m = m0 + ty*4 + i;
        float4 o = make_float4(acc[i][0]*inv, acc[i][1]*inv,
                               acc[i][2]*inv, acc[i][3]*inv);
        *(float4*)(out + (size_t)m * NB + b*E_DIM + h*D_HEAD + tx*4) = o;
    }
}

// ---------------------------------------------------------------------------
// x = query + ob ; LayerNorm(last dim) * gamma + beta.
// ---------------------------------------------------------------------------
__global__ __launch_bounds__(256) void addln_kernel(
    const float* __restrict__ qin, const float* __restrict__ ob,
    const float* __restrict__ gamma, const float* __restrict__ beta,
    float* __restrict__ out)
{
    const int row = blockIdx.x;
    const int tid = threadIdx.x;
    const size_t base = (size_t)row * E_DIM;

    const float4 a = *(const float4*)(qin + base + tid*4);
    const float4 c = *(const float4*)(ob  + base + tid*4);
    const float e0 = a.x + c.x, e1 = a.y + c.y, e2 = a.z + c.z, e3 = a.w + c.w;
    float s  = e0 + e1 + e2 + e3;
    float ss = e0*e0 + e1*e1 + e2*e2 + e3*e3;
#pragma unroll
    for (int off = 16; off > 0; off >>= 1) {
        s  += __shfl_xor_sync(0xffffffffu, s,  off);
        ss += __shfl_xor_sync(0xffffffffu, ss, off);
    }
    __shared__ float sw[8], ssw[8], red[2];
    const int wid = tid >> 5, lane = tid & 31;
    if (lane == 0) { sw[wid] = s; ssw[wid] = ss; }
    __syncthreads();
    if (tid == 0) {
        float S2 = 0.f, SS = 0.f;
        for (int i = 0; i < 8; i++) { S2 += sw[i]; SS += ssw[i]; }
        red[0] = S2; red[1] = SS;
    }
    __syncthreads();
    const float mu  = red[0] * (1.0f / E_DIM);
    const float var = red[1] * (1.0f / E_DIM) - mu * mu;
    const float r   = rsqrtf(var + 1e-5f);
    const float4 g  = *(const float4*)(gamma + tid*4);
    const float4 bt = *(const float4*)(beta  + tid*4);
    float4 o;
    o.x = (e0 - mu) * r * g.x + bt.x;
    o.y = (e1 - mu) * r * g.y + bt.y;
    o.z = (e2 - mu) * r * g.z + bt.z;
    o.w = (e3 - mu) * r * g.w + bt.w;
    *(float4*)(out + base + tid*4) = o;
}

// ---------------------------------------------------------------------------
extern "C" void kernel_launch(void* const* d_in, const int* in_sizes, int n_in,
                              void* d_out, int out_size)
{
    const float* query    = (const float*)d_in[0];
    const float* key      = (const float*)d_in[1];
    const float* value    = (const float*)d_in[2];
    const float* Wq       = (const float*)d_in[3];
    const float* Wk       = (const float*)d_in[4];
    const float* Wv       = (const float*)d_in[5];
    const float* in_proj  = (const float*)d_in[6];
    const float* out_proj = (const float*)d_in[7];
    const float* proj     = (const float*)d_in[8];
    const float* gamma    = (const float*)d_in[9];
    const float* beta     = (const float*)d_in[10];
    float* out = (float*)d_out;

    float *pa, *pb, *pc, *pqp, *pkp, *pvp;
    __nv_bfloat16* pwbf;
    cudaGetSymbolAddress((void**)&pa,  g_a);
    cudaGetSymbolAddress((void**)&pb,  g_b);
    cudaGetSymbolAddress((void**)&pc,  g_c);
    cudaGetSymbolAddress((void**)&pqp, g_qp);
    cudaGetSymbolAddress((void**)&pkp, g_kp);
    cudaGetSymbolAddress((void**)&pvp, g_vp);
    cudaGetSymbolAddress((void**)&pwbf, g_wbf);

    cudaFuncSetAttribute(attn_kernel,
                         cudaFuncAttributeMaxDynamicSharedMemorySize, ATTN_SMEM);

    const size_t M1 = 1u << 20;

    // weights fp32 -> bf16 (8M elements)
    convw_kernel<<<8192, 256>>>(Wq, Wk, Wv, in_proj, out_proj, proj, pwbf);

    const dim3 gg(8, 64);   // N blocks (8 x 128), M blocks (64 x 128)

    // q,k,v = swap(query/key/value) @ W{q,k,v}.T  -> [S,B,E]
    gemm_mma<<<gg, 256>>>(query, pwbf + 0*M1, pa, B_SZ, S_LEN*E_DIM, E_DIM);
    gemm_mma<<<gg, 256>>>(key,   pwbf + 1*M1, pb, B_SZ, S_LEN*E_DIM, E_DIM);
    gemm_mma<<<gg, 256>>>(value, pwbf + 2*M1, pc, B_SZ, S_LEN*E_DIM, E_DIM);

    // RoPE in-place on q (pa) and k (pb); position index = b
    rope_kernel<<<(S_LEN * B_SZ * H_NUM * 32) / 256, 256>>>(pa, pb);

    // in_proj splits
    gemm_mma<<<gg, 256>>>(pa, pwbf + 3*M1, pqp, 1, 0, E_DIM);
    gemm_mma<<<gg, 256>>>(pb, pwbf + 4*M1, pkp, 1, 0, E_DIM);
    gemm_mma<<<gg, 256>>>(pc, pwbf + 5*M1, pvp, 1, 0, E_DIM);

    // attention -> pa  [S,B,E]
    const dim3 ga(S_LEN / 64, B_SZ * H_NUM);
    attn_kernel<<<ga, 256, ATTN_SMEM>>>(pqp, pkp, pvp, pa);

    // out_proj
    gemm_mma<<<gg, 256>>>(pa, pwbf + 6*M1, pb, 1, 0, E_DIM);

    // final proj with [S,B,E] -> [B,S,E] gather: row m=b*S+s at s*NB + b*E
    gemm_mma<<<gg, 256>>>(pb, pwbf + 7*M1, pc, S_LEN, NB, E_DIM);

    // residual + layernorm -> out [B,S,O]
    addln_kernel<<<B_SZ * S_LEN, 256>>>(query, pc, gamma, beta, out);
}

// round 4
// speedup vs baseline: 5.3900x; 2.0457x over previous
#include <cuda_runtime.h>
#include <cuda_bf16.h>
#include <cstdint>

#define S_LEN  1024
#define B_SZ   8
#define E_DIM  1024
#define H_NUM  16
#define D_HEAD 64
#define NB     (B_SZ * E_DIM)           /* 8192 = s-stride in [S,B,E] */
#define NBUF   (S_LEN * B_SZ * E_DIM)   /* 8M floats = 32 MB */

// Scratch (no allocations allowed)
__device__ float g_a[NBUF];
__device__ float g_b[NBUF];
__device__ float g_c[NBUF];
__device__ float g_qp[NBUF];   // used as bf16 (16MB of 32MB)
__device__ float g_kp[NBUF];
__device__ float g_vp[NBUF];
__device__ __nv_bfloat16 g_wbf[8u * 1024u * 1024u];   // bf16 weights, 8 x 1M

// ===========================================================================
// Family-portable PTX helpers (NO tcgen05 — harness compiles compute_103)
// ===========================================================================
__device__ __forceinline__ uint32_t smem_u32(const void* p) {
    uint32_t a;
    asm("{ .reg .u64 t; cvta.to.shared.u64 t, %1; cvt.u32.u64 %0, t; }"
        : "=r"(a) : "l"(p));
    return a;
}

#define LDSM_X4(d, addr)                                                        \
    asm volatile("ldmatrix.sync.aligned.m8n8.x4.shared.b16 {%0,%1,%2,%3}, [%4];"\
        : "=r"((d)[0]), "=r"((d)[1]), "=r"((d)[2]), "=r"((d)[3]) : "r"(addr))

#define LDSM_X4T(d, addr)                                                       \
    asm volatile("ldmatrix.sync.aligned.m8n8.x4.trans.shared.b16 {%0,%1,%2,%3}, [%4];"\
        : "=r"((d)[0]), "=r"((d)[1]), "=r"((d)[2]), "=r"((d)[3]) : "r"(addr))

#define MMA_BF16(ac, a, b0, b1)                                                 \
    asm volatile("mma.sync.aligned.m16n8k16.row.col.f32.bf16.bf16.f32 "         \
        "{%0,%1,%2,%3}, {%4,%5,%6,%7}, {%8,%9}, {%0,%1,%2,%3};"                 \
        : "+f"((ac)[0]), "+f"((ac)[1]), "+f"((ac)[2]), "+f"((ac)[3])            \
        : "r"((a)[0]), "r"((a)[1]), "r"((a)[2]), "r"((a)[3]),                   \
          "r"(b0), "r"(b1))

#define CP_ASYNC16(s, g)                                                        \
    asm volatile("cp.async.cg.shared.global [%0], [%1], 16;" :: "r"(s), "l"(g))
#define CP_COMMIT() asm volatile("cp.async.commit_group;" ::: "memory")
#define CP_WAIT0()  asm volatile("cp.async.wait_group 0;" ::: "memory")

__device__ __forceinline__ void sts_bf16x8(uint32_t addr, float4 lo, float4 hi) {
    __nv_bfloat162 p0 = __floats2bfloat162_rn(lo.x, lo.y);
    __nv_bfloat162 p1 = __floats2bfloat162_rn(lo.z, lo.w);
    __nv_bfloat162 p2 = __floats2bfloat162_rn(hi.x, hi.y);
    __nv_bfloat162 p3 = __floats2bfloat162_rn(hi.z, hi.w);
    asm volatile("st.shared.v4.b32 [%0], {%1,%2,%3,%4};"
        :: "r"(addr),
           "r"(*reinterpret_cast<uint32_t*>(&p0)),
           "r"(*reinterpret_cast<uint32_t*>(&p1)),
           "r"(*reinterpret_cast<uint32_t*>(&p2)),
           "r"(*reinterpret_cast<uint32_t*>(&p3)));
}

__device__ __forceinline__ uint32_t packbf(float x, float y) {
    __nv_bfloat162 t = __floats2bfloat162_rn(x, y);
    return *reinterpret_cast<uint32_t*>(&t);
}

// ===========================================================================
// bf16 mma.sync GEMM: C[m, n] = sum_k A_row(m)[k] * Bw[n*1024 + k]
// Template OUTBF: write fp32 (false) or bf16 (true) C.
// ===========================================================================
#define TSTRIDE 40            /* bf16 elements per padded row */
#define TBYTES  (128 * TSTRIDE * 2)   /* 10240 bytes per tile buffer */

template<bool OUTBF>
__global__ __launch_bounds__(256, 2) void gemm_mma(
    const float* __restrict__ A, const __nv_bfloat16* __restrict__ Bw,
    void* __restrict__ Cv, int P, int sa0, int sa1)
{
    __shared__ __align__(16) __nv_bfloat16 As[2][128 * TSTRIDE];
    __shared__ __align__(16) __nv_bfloat16 Bs[2][128 * TSTRIDE];

    const int tid  = threadIdx.x;
    const int lane = tid & 31;
    const int w    = tid >> 5;
    const int wm   = w >> 1;
    const int wn   = w & 1;
    const int m_blk = blockIdx.y << 7;
    const int n_blk = blockIdx.x << 7;

    const int r0 = tid >> 2;
    const int q8 = (tid & 3) << 3;

    const int am0 = m_blk + r0, am1 = am0 + 64;
    const float* ap0 = A + (size_t)(am0 % P) * sa0 + (size_t)(am0 / P) * sa1 + q8;
    const float* ap1 = A + (size_t)(am1 % P) * sa0 + (size_t)(am1 / P) * sa1 + q8;
    const __nv_bfloat16* bp0 = Bw + (size_t)(n_blk + r0) * 1024 + q8;
    const __nv_bfloat16* bp1 = Bw + (size_t)(n_blk + r0 + 64) * 1024 + q8;

    const uint32_t sa = smem_u32(As);
    const uint32_t sb = smem_u32(Bs);
    const uint32_t a_sts0 = sa + (uint32_t)(r0 * TSTRIDE + q8) * 2;
    const uint32_t a_sts1 = sa + (uint32_t)((r0 + 64) * TSTRIDE + q8) * 2;
    const uint32_t b_sts0 = sb + (uint32_t)(r0 * TSTRIDE + q8) * 2;
    const uint32_t b_sts1 = sb + (uint32_t)((r0 + 64) * TSTRIDE + q8) * 2;

    const uint32_t a_lm = sa +
        (uint32_t)((wm * 32 + (lane & 15)) * TSTRIDE) * 2 + ((lane >> 4) << 4);
    const uint32_t b_lm = sb +
        (uint32_t)((wn * 64 + (((lane >> 4) & 1) << 3) + (lane & 7)) * TSTRIDE) * 2
        + (((lane >> 3) & 1) << 4);

    float acc[2][8][4];
#pragma unroll
    for (int mt = 0; mt < 2; mt++)
#pragma unroll
        for (int nt = 0; nt < 8; nt++)
#pragma unroll
            for (int j = 0; j < 4; j++) acc[mt][nt][j] = 0.f;

    float4 na00 = *(const float4*)(ap0);
    float4 na01 = *(const float4*)(ap0 + 4);
    float4 na10 = *(const float4*)(ap1);
    float4 na11 = *(const float4*)(ap1 + 4);
    CP_ASYNC16(b_sts0, bp0);
    CP_ASYNC16(b_sts1, bp1);
    CP_COMMIT();
    sts_bf16x8(a_sts0, na00, na01);
    sts_bf16x8(a_sts1, na10, na11);
    CP_WAIT0();
    __syncthreads();

    for (int i = 0; i < 32; i++) {
        const int p = i & 1, q = p ^ 1;
        if (i < 31) {
            const int ko = (i + 1) << 5;
            na00 = *(const float4*)(ap0 + ko);
            na01 = *(const float4*)(ap0 + ko + 4);
            na10 = *(const float4*)(ap1 + ko);
            na11 = *(const float4*)(ap1 + ko + 4);
            CP_ASYNC16(b_sts0 + q * TBYTES, bp0 + ko);
            CP_ASYNC16(b_sts1 + q * TBYTES, bp1 + ko);
            CP_COMMIT();
        }

        const uint32_t ab = a_lm + p * TBYTES;
        const uint32_t bb = b_lm + p * TBYTES;
#pragma unroll
        for (int ks = 0; ks < 2; ks++) {
            uint32_t af0[4], af1[4];
            LDSM_X4(af0, ab + ks * 32);
            LDSM_X4(af1, ab + ks * 32 + 16 * TSTRIDE * 2);
            uint32_t bf[4][4];
#pragma unroll
            for (int bt = 0; bt < 4; bt++)
                LDSM_X4(bf[bt], bb + ks * 32 + bt * 16 * TSTRIDE * 2);
#pragma unroll
            for (int nt = 0; nt < 8; nt++) {
                const uint32_t bb0 = (nt & 1) ? bf[nt >> 1][2] : bf[nt >> 1][0];
                const uint32_t bb1 = (nt & 1) ? bf[nt >> 1][3] : bf[nt >> 1][1];
                MMA_BF16(acc[0][nt], af0, bb0, bb1);
                MMA_BF16(acc[1][nt], af1, bb0, bb1);
            }
        }

        if (i < 31) {
            sts_bf16x8(a_sts0 + q * TBYTES, na00, na01);
            sts_bf16x8(a_sts1 + q * TBYTES, na10, na11);
            CP_WAIT0();
        }
        __syncthreads();
    }

    const int crow = m_blk + wm * 32 + (lane >> 2);
    const int ccol = n_blk + wn * 64 + ((lane & 3) << 1);
    if (OUTBF) {
        __nv_bfloat16* C = (__nv_bfloat16*)Cv;
#pragma unroll
        for (int mt = 0; mt < 2; mt++)
#pragma unroll
            for (int nt = 0; nt < 8; nt++) {
                __nv_bfloat16* cp = C + (size_t)(crow + mt * 16) * 1024 + ccol + nt * 8;
                *(uint32_t*)cp = packbf(acc[mt][nt][0], acc[mt][nt][1]);
                *(uint32_t*)(cp + 8 * 1024) = packbf(acc[mt][nt][2], acc[mt][nt][3]);
            }
    } else {
        float* C = (float*)Cv;
#pragma unroll
        for (int mt = 0; mt < 2; mt++)
#pragma unroll
            for (int nt = 0; nt < 8; nt++) {
                float* cp = C + (size_t)(crow + mt * 16) * 1024 + ccol + nt * 8;
                *(float2*)cp = make_float2(acc[mt][nt][0], acc[mt][nt][1]);
                *(float2*)(cp + 8 * 1024) = make_float2(acc[mt][nt][2], acc[mt][nt][3]);
            }
    }
}

// ===========================================================================
// Tensor-core flash attention, bf16 in / fp32 out, online softmax.
// Grid (S/64, B*H). 128 threads = 4 warps; warp = 16 q-rows x 128 keys.
// qp/kp/vp bf16 [S,B,H,D] (s-stride NB). out fp32 same layout.
// ===========================================================================
#define AST 72                 /* padded row: 72 bf16 = 144 B */

__global__ __launch_bounds__(128) void attn_mma(
    const __nv_bfloat16* __restrict__ qp, const __nv_bfloat16* __restrict__ kp,
    const __nv_bfloat16* __restrict__ vp, float* __restrict__ out)
{
    __shared__ __align__(16) __nv_bfloat16 Qs[64 * AST];
    __shared__ __align__(16) __nv_bfloat16 Ks[128 * AST];
    __shared__ __align__(16) __nv_bfloat16 Vs[128 * AST];

    const int tid = threadIdx.x, lane = tid & 31, w = tid >> 5;
    const int bh = blockIdx.y, b = bh >> 4, h = bh & 15;
    const int m0 = blockIdx.x << 6;
    const size_t hb = (size_t)b * E_DIM + h * D_HEAD;
    const __nv_bfloat16* qb = qp + hb;
    const __nv_bfloat16* kb = kp + hb;
    const __nv_bfloat16* vb = vp + hb;

    const uint32_t sQ = smem_u32(Qs), sK = smem_u32(Ks), sV = smem_u32(Vs);

    // Q: 64 rows x 8 segs(16B) = 512 chunks / 128 threads = 4 each
#pragma unroll
    for (int j = 0; j < 4; j++) {
        const int c = tid + 128 * j;
        const int rr = c >> 3, sg = (c & 7) << 3;
        CP_ASYNC16(sQ + (uint32_t)(rr * 144 + sg * 2),
                   qb + (size_t)(m0 + rr) * NB + sg);
    }
    CP_COMMIT();

    // ldmatrix lane bases
    const uint32_t aQ = sQ + (uint32_t)((w * 16 + (lane & 15)) * 144) + ((lane >> 4) << 4);
    const uint32_t bK = sK + (uint32_t)(((((lane >> 4) & 1) << 3) + (lane & 7)) * 144)
                           + (((lane >> 3) & 1) << 4);
    const uint32_t bV = sV + (uint32_t)(((lane & 7) + (((lane >> 3) & 1) << 3)) * 144)
                           + ((lane >> 4) << 4);

    float m0r = -1e30f, m1r = -1e30f, l0 = 0.f, l1 = 0.f;
    float o[8][4];
#pragma unroll
    for (int nt = 0; nt < 8; nt++)
#pragma unroll
        for (int j = 0; j < 4; j++) o[nt][j] = 0.f;

    for (int t0 = 0; t0 < S_LEN; t0 += 128) {
        __syncthreads();     // previous-iter compute done before overwrite
#pragma unroll
        for (int j = 0; j < 8; j++) {
            const int c = tid + 128 * j;
            const int rr = c >> 3, sg = (c & 7) << 3;
            const uint32_t so = (uint32_t)(rr * 144 + sg * 2);
            const size_t go = (size_t)(t0 + rr) * NB + sg;
            CP_ASYNC16(sK + so, kb + go);
            CP_ASYNC16(sV + so, vb + go);
        }
        CP_COMMIT();
        CP_WAIT0();
        __syncthreads();

        // S = Q K^T  (16 rows x 128 keys per warp)
        float s[16][4];
#pragma unroll
        for (int nt = 0; nt < 16; nt++)
#pragma unroll
            for (int j = 0; j < 4; j++) s[nt][j] = 0.f;

#pragma unroll
        for (int ks = 0; ks < 4; ks++) {
            uint32_t aq[4];
            LDSM_X4(aq, aQ + ks * 32);
#pragma unroll
            for (int bt = 0; bt < 8; bt++) {
                uint32_t bk[4];
                LDSM_X4(bk, bK + bt * (16 * 144) + ks * 32);
                MMA_BF16(s[2 * bt], aq, bk[0], bk[1]);
                MMA_BF16(s[2 * bt + 1], aq, bk[2], bk[3]);
            }
        }

        // online softmax (rows r = lane>>2 and r+8)
        float mx0 = m0r, mx1 = m1r;
#pragma unroll
        for (int nt = 0; nt < 16; nt++) {
            s[nt][0] *= 0.125f; s[nt][1] *= 0.125f;
            s[nt][2] *= 0.125f; s[nt][3] *= 0.125f;
            mx0 = fmaxf(mx0, fmaxf(s[nt][0], s[nt][1]));
            mx1 = fmaxf(mx1, fmaxf(s[nt][2], s[nt][3]));
        }
        mx0 = fmaxf(mx0, __shfl_xor_sync(0xffffffffu, mx0, 1, 4));
        mx0 = fmaxf(mx0, __shfl_xor_sync(0xffffffffu, mx0, 2, 4));
        mx1 = fmaxf(mx1, __shfl_xor_sync(0xffffffffu, mx1, 1, 4));
        mx1 = fmaxf(mx1, __shfl_xor_sync(0xffffffffu, mx1, 2, 4));
        const float f0 = __expf(m0r - mx0), f1 = __expf(m1r - mx1);
        float r0 = 0.f, r1 = 0.f;
#pragma unroll
        for (int nt = 0; nt < 16; nt++) {
            s[nt][0] = __expf(s[nt][0] - mx0);
            s[nt][1] = __expf(s[nt][1] - mx0);
            s[nt][2] = __expf(s[nt][2] - mx1);
            s[nt][3] = __expf(s[nt][3] - mx1);
            r0 += s[nt][0] + s[nt][1];
            r1 += s[nt][2] + s[nt][3];
        }
        r0 += __shfl_xor_sync(0xffffffffu, r0, 1, 4);
        r0 += __shfl_xor_sync(0xffffffffu, r0, 2, 4);
        r1 += __shfl_xor_sync(0xffffffffu, r1, 1, 4);
        r1 += __shfl_xor_sync(0xffffffffu, r1, 2, 4);
        l0 = l0 * f0 + r0; l1 = l1 * f1 + r1;
        m0r = mx0; m1r = mx1;
#pragma unroll
        for (int nt = 0; nt < 8; nt++) {
            o[nt][0] *= f0; o[nt][1] *= f0;
            o[nt][2] *= f1; o[nt][3] *= f1;
        }

        // O += P V   (P from S fragments, V via ldmatrix.trans)
#pragma unroll
        for (int kk = 0; kk < 8; kk++) {
            uint32_t pa[4];
            pa[0] = packbf(s[2 * kk][0], s[2 * kk][1]);
            pa[1] = packbf(s[2 * kk][2], s[2 * kk][3]);
            pa[2] = packbf(s[2 * kk + 1][0], s[2 * kk + 1][1]);
            pa[3] = packbf(s[2 * kk + 1][2], s[2 * kk + 1][3]);
            const uint32_t vbase = bV + kk * (16 * 144);
#pragma unroll
            for (int vt = 0; vt < 4; vt++) {
                uint32_t bv[4];
                LDSM_X4T(bv, vbase + vt * 32);
                MMA_BF16(o[2 * vt], pa, bv[0], bv[1]);
                MMA_BF16(o[2 * vt + 1], pa, bv[2], bv[3]);
            }
        }
    }

    // epilogue
    const int row0 = m0 + w * 16 + (lane >> 2);
    const int col = (lane & 3) << 1;
    const float i0 = 1.f / l0, i1 = 1.f / l1;
    float* ob0 = out + (size_t)row0 * NB + hb;
    float* ob1 = out + (size_t)(row0 + 8) * NB + hb;
#pragma unroll
    for (int nt = 0; nt < 8; nt++) {
        *(float2*)(ob0 + nt * 8 + col) = make_float2(o[nt][0] * i0, o[nt][1] * i0);
        *(float2*)(ob1 + nt * 8 + col) = make_float2(o[nt][2] * i1, o[nt][3] * i1);
    }
}

// ===========================================================================
// Weight fp32 -> bf16 convert: 8M elements into g_wbf
// ===========================================================================
__global__ __launch_bounds__(256) void convw_kernel(
    const float* __restrict__ Wq, const float* __restrict__ Wk,
    const float* __restrict__ Wv, const float* __restrict__ inp,
    const float* __restrict__ outp, const float* __restrict__ projw,
    __nv_bfloat16* __restrict__ dst)
{
    const int idx = blockIdx.x * 256 + threadIdx.x;
    const size_t e = (size_t)idx << 2;
    const int seg = (int)(e >> 20);
    const size_t off = e & 0xFFFFFu;
    const float* src;
    switch (seg) {
        case 0: src = Wq; break;
        case 1: src = Wk; break;
        case 2: src = Wv; break;
        case 3: case 4: case 5: src = inp + ((size_t)(seg - 3) << 20); break;
        case 6: src = outp; break;
        default: src = projw; break;
    }
    const float4 v = *(const float4*)(src + off);
    uint2 pv;
    pv.x = packbf(v.x, v.y);
    pv.y = packbf(v.z, v.w);
    *reinterpret_cast<uint2*>(dst + e) = pv;
}

// ---------------------------------------------------------------------------
// RoPE, position index = batch b (per reference!). In-place on q and k [S,B,E].
// ---------------------------------------------------------------------------
__global__ __launch_bounds__(256) void rope_kernel(float* __restrict__ q,
                                                   float* __restrict__ k)
{
    const int idx = blockIdx.x * 256 + threadIdx.x;
    const int j  = idx & 31;
    const int h  = (idx >> 5) & (H_NUM - 1);
    const int sb = idx >> 9;
    const int b  = sb & (B_SZ - 1);
    const size_t base = (size_t)sb * E_DIM + h * D_HEAD;
    const float inv = expf((float)j * (-0.28782313662425575f)); // ln(1e4)/32
    const float ang = (float)b * inv;
    const float c = cosf(ang), s = sinf(ang);
    float x1 = q[base + j], x2 = q[base + j + 32];
    q[base + j]      = x1 * c - x2 * s;
    q[base + j + 32] = x2 * c + x1 * s;
    x1 = k[base + j]; x2 = k[base + j + 32];
    k[base + j]      = x1 * c - x2 * s;
    k[base + j + 32] = x2 * c + x1 * s;
}

// ---------------------------------------------------------------------------
// x = query + ob ; LayerNorm(last dim) * gamma + beta.
// ---------------------------------------------------------------------------
__global__ __launch_bounds__(256) void addln_kernel(
    const float* __restrict__ qin, const float* __restrict__ ob,
    const float* __restrict__ gamma, const float* __restrict__ beta,
    float* __restrict__ out)
{
    const int row = blockIdx.x;
    const int tid = threadIdx.x;
    const size_t base = (size_t)row * E_DIM;

    const float4 a = *(const float4*)(qin + base + tid*4);
    const float4 c = *(const float4*)(ob  + base + tid*4);
    const float e0 = a.x + c.x, e1 = a.y + c.y, e2 = a.z + c.z, e3 = a.w + c.w;
    float s  = e0 + e1 + e2 + e3;
    float ss = e0*e0 + e1*e1 + e2*e2 + e3*e3;
#pragma unroll
    for (int off = 16; off > 0; off >>= 1) {
        s  += __shfl_xor_sync(0xffffffffu, s,  off);
        ss += __shfl_xor_sync(0xffffffffu, ss, off);
    }
    __shared__ float sw[8], ssw[8], red[2];
    const int wid = tid >> 5, lane = tid & 31;
    if (lane == 0) { sw[wid] = s; ssw[wid] = ss; }
    __syncthreads();
    if (tid == 0) {
        float S2 = 0.f, SS = 0.f;
        for (int i = 0; i < 8; i++) { S2 += sw[i]; SS += ssw[i]; }
        red[0] = S2; red[1] = SS;
    }
    __syncthreads();
    const float mu  = red[0] * (1.0f / E_DIM);
    const float var = red[1] * (1.0f / E_DIM) - mu * mu;
    const float r   = rsqrtf(var + 1e-5f);
    const float4 g  = *(const float4*)(gamma + tid*4);
    const float4 bt = *(const float4*)(beta  + tid*4);
    float4 o;
    o.x = (e0 - mu) * r * g.x + bt.x;
    o.y = (e1 - mu) * r * g.y + bt.y;
    o.z = (e2 - mu) * r * g.z + bt.z;
    o.w = (e3 - mu) * r * g.w + bt.w;
    *(float4*)(out + base + tid*4) = o;
}

// ---------------------------------------------------------------------------
extern "C" void kernel_launch(void* const* d_in, const int* in_sizes, int n_in,
                              void* d_out, int out_size)
{
    const float* query    = (const float*)d_in[0];
    const float* key      = (const float*)d_in[1];
    const float* value    = (const float*)d_in[2];
    const float* Wq       = (const float*)d_in[3];
    const float* Wk       = (const float*)d_in[4];
    const float* Wv       = (const float*)d_in[5];
    const float* in_proj  = (const float*)d_in[6];
    const float* out_proj = (const float*)d_in[7];
    const float* proj     = (const float*)d_in[8];
    const float* gamma    = (const float*)d_in[9];
    const float* beta     = (const float*)d_in[10];
    float* out = (float*)d_out;

    float *pa, *pb, *pc, *pqp, *pkp, *pvp;
    __nv_bfloat16* pwbf;
    cudaGetSymbolAddress((void**)&pa,  g_a);
    cudaGetSymbolAddress((void**)&pb,  g_b);
    cudaGetSymbolAddress((void**)&pc,  g_c);
    cudaGetSymbolAddress((void**)&pqp, g_qp);
    cudaGetSymbolAddress((void**)&pkp, g_kp);
    cudaGetSymbolAddress((void**)&pvp, g_vp);
    cudaGetSymbolAddress((void**)&pwbf, g_wbf);

    __nv_bfloat16* qpb = (__nv_bfloat16*)pqp;
    __nv_bfloat16* kpb = (__nv_bfloat16*)pkp;
    __nv_bfloat16* vpb = (__nv_bfloat16*)pvp;

    const size_t M1 = 1u << 20;

    // weights fp32 -> bf16 (8M elements)
    convw_kernel<<<8192, 256>>>(Wq, Wk, Wv, in_proj, out_proj, proj, pwbf);

    const dim3 gg(8, 64);   // N blocks (8 x 128), M blocks (64 x 128)

    // q,k,v = swap(query/key/value) @ W{q,k,v}.T  -> [S,B,E] fp32
    gemm_mma<false><<<gg, 256>>>(query, pwbf + 0*M1, pa, B_SZ, S_LEN*E_DIM, E_DIM);
    gemm_mma<false><<<gg, 256>>>(key,   pwbf + 1*M1, pb, B_SZ, S_LEN*E_DIM, E_DIM);
    gemm_mma<false><<<gg, 256>>>(value, pwbf + 2*M1, pc, B_SZ, S_LEN*E_DIM, E_DIM);

    // RoPE in-place on q (pa) and k (pb); position index = b
    rope_kernel<<<(S_LEN * B_SZ * H_NUM * 32) / 256, 256>>>(pa, pb);

    // in_proj splits -> bf16 outputs for attention
    gemm_mma<true><<<gg, 256>>>(pa, pwbf + 3*M1, qpb, 1, 0, E_DIM);
    gemm_mma<true><<<gg, 256>>>(pb, pwbf + 4*M1, kpb, 1, 0, E_DIM);
    gemm_mma<true><<<gg, 256>>>(pc, pwbf + 5*M1, vpb, 1, 0, E_DIM);

    // tensor-core attention -> pa  [S,B,E] fp32
    const dim3 ga(S_LEN / 64, B_SZ * H_NUM);   // (16, 128)
    attn_mma<<<ga, 128>>>(qpb, kpb, vpb, pa);

    // out_proj
    gemm_mma<false><<<gg, 256>>>(pa, pwbf + 6*M1, pb, 1, 0, E_DIM);

    // final proj with [S,B,E] -> [B,S,E] gather: row m=b*S+s at s*NB + b*E
    gemm_mma<false><<<gg, 256>>>(pb, pwbf + 7*M1, pc, S_LEN, NB, E_DIM);

    // residual + layernorm -> out [B,S,O]
    addln_kernel<<<B_SZ * S_LEN, 256>>>(query, pc, gamma, beta, out);
}

// round 7
// speedup vs baseline: 6.3115x; 1.1710x over previous
#include <cuda_runtime.h>
#include <cuda_bf16.h>
#include <cstdint>

#define S_LEN  1024
#define B_SZ   8
#define E_DIM  1024
#define H_NUM  16
#define D_HEAD 64
#define NB     (B_SZ * E_DIM)           /* 8192 = s-stride in [S,B,E] */
#define NBUF   (S_LEN * B_SZ * E_DIM)   /* 8M floats = 32 MB */
#define M8     (1u << 23)               /* 8M elements */

typedef __nv_bfloat16 bf16;

// Scratch (no allocations allowed) — each 32MB fp32 buffer holds two 8M bf16 tensors
__device__ float g_a[NBUF];    // lo: bfQin | hi: bfKin ; later fp32 final-proj out
__device__ float g_b[NBUF];    // lo: bfVin | hi: q_bf
__device__ float g_c[NBUF];    // lo: k_bf  | hi: v_bf
__device__ float g_qp[NBUF];   // lo: qp    | hi: kp
__device__ float g_kp[NBUF];   // lo: vp    | hi: O_bf
__device__ float g_vp[NBUF];   // lo: ob1_bf
__device__ bf16  g_wbf[8u * 1024u * 1024u];   // bf16 weights, 8 x 1M

// ===========================================================================
// Family-portable PTX helpers (NO tcgen05 — harness compiles compute_103)
// ===========================================================================
__device__ __forceinline__ uint32_t smem_u32(const void* p) {
    uint32_t a;
    asm("{ .reg .u64 t; cvta.to.shared.u64 t, %1; cvt.u32.u64 %0, t; }"
        : "=r"(a) : "l"(p));
    return a;
}

#define LDSM_X4(d, addr)                                                        \
    asm volatile("ldmatrix.sync.aligned.m8n8.x4.shared.b16 {%0,%1,%2,%3}, [%4];"\
        : "=r"((d)[0]), "=r"((d)[1]), "=r"((d)[2]), "=r"((d)[3]) : "r"(addr))

#define LDSM_X4T(d, addr)                                                       \
    asm volatile("ldmatrix.sync.aligned.m8n8.x4.trans.shared.b16 {%0,%1,%2,%3}, [%4];"\
        : "=r"((d)[0]), "=r"((d)[1]), "=r"((d)[2]), "=r"((d)[3]) : "r"(addr))

#define MMA_BF16(ac, a, b0, b1)                                                 \
    asm volatile("mma.sync.aligned.m16n8k16.row.col.f32.bf16.bf16.f32 "         \
        "{%0,%1,%2,%3}, {%4,%5,%6,%7}, {%8,%9}, {%0,%1,%2,%3};"                 \
        : "+f"((ac)[0]), "+f"((ac)[1]), "+f"((ac)[2]), "+f"((ac)[3])            \
        : "r"((a)[0]), "r"((a)[1]), "r"((a)[2]), "r"((a)[3]),                   \
          "r"(b0), "r"(b1))

#define CP_ASYNC16(s, g)                                                        \
    asm volatile("cp.async.cg.shared.global [%0], [%1], 16;" :: "r"(s), "l"(g))
#define CP_COMMIT() asm volatile("cp.async.commit_group;" ::: "memory")
#define CP_WAIT0()  asm volatile("cp.async.wait_group 0;" ::: "memory")

__device__ __forceinline__ uint32_t packbf(float x, float y) {
    __nv_bfloat162 t = __floats2bfloat162_rn(x, y);
    return *reinterpret_cast<uint32_t*>(&t);
}

// ===========================================================================
// All-bf16 mma.sync GEMM: C[m, n] = sum_k A_row(m)[k] * Bw[n*1024 + k]
// A, Bw bf16, both via cp.async. M=8192, N=1024, K=1024.
// CTA 128x128, K-chunk 64 (4 ldmatrix k-steps), double-buffered dynamic smem.
// Padded rows: 72 bf16 = 144 B. A row m at A + (m%P)*sa0 + (m/P)*sa1.
// OUTBF: write bf16 (true) or fp32 (false) C.
// ===========================================================================
#define GTB   (128 * 72 * 2)     /* 18432 B per tile */
#define STAGE (2 * GTB)          /* 36864 B per stage (A + B) */
#define GEMM_SMEM (2 * STAGE)    /* 73728 B */

template<bool OUTBF>
__global__ __launch_bounds__(256, 2) void gemm_bf(
    const bf16* __restrict__ A, const bf16* __restrict__ Bw,
    void* __restrict__ Cv, int P, int sa0, int sa1)
{
    extern __shared__ __align__(16) char smp[];
    const uint32_t s0 = smem_u32(smp);

    const int tid  = threadIdx.x;
    const int lane = tid & 31;
    const int w    = tid >> 5;
    const int wm   = w >> 1;          // 0..3
    const int wn   = w & 1;           // 0..1
    const int m_blk = blockIdx.y << 7;
    const int n_blk = blockIdx.x << 7;

    // 1024 chunks (8 bf16 each) per tile / 256 threads = 4 per thread
    const bf16* apt[4];
    const bf16* bpt[4];
    uint32_t ast[4], bst[4];
#pragma unroll
    for (int j = 0; j < 4; j++) {
        const int c = tid + 256 * j;
        const int row = c >> 3, sg = (c & 7) << 3;
        const int m = m_blk + row;
        apt[j] = A + (size_t)(m % P) * sa0 + (size_t)(m / P) * sa1 + sg;
        bpt[j] = Bw + (size_t)(n_blk + row) * 1024 + sg;
        ast[j] = s0 + (uint32_t)(row * 144 + sg * 2);
        bst[j] = s0 + GTB + (uint32_t)(row * 144 + sg * 2);
    }

    // ldmatrix lane bases
    const uint32_t a_lm = s0 +
        (uint32_t)((wm * 32 + (lane & 15)) * 144) + ((lane >> 4) << 4);
    const uint32_t b_lm = s0 + GTB +
        (uint32_t)((wn * 64 + (((lane >> 4) & 1) << 3) + (lane & 7)) * 144)
        + (((lane >> 3) & 1) << 4);

    float acc[2][8][4];
#pragma unroll
    for (int mt = 0; mt < 2; mt++)
#pragma unroll
        for (int nt = 0; nt < 8; nt++)
#pragma unroll
            for (int j = 0; j < 4; j++) acc[mt][nt][j] = 0.f;

    // prologue: stage 0 into buffer 0
#pragma unroll
    for (int j = 0; j < 4; j++) {
        CP_ASYNC16(ast[j], apt[j]);
        CP_ASYNC16(bst[j], bpt[j]);
    }
    CP_COMMIT();
    CP_WAIT0();
    __syncthreads();

    for (int i = 0; i < 16; i++) {
        const int p = i & 1, q = p ^ 1;
        if (i < 15) {
            const int ko = (i + 1) << 6;     // K offset in elements
#pragma unroll
            for (int j = 0; j < 4; j++) {
                CP_ASYNC16(ast[j] + q * STAGE, apt[j] + ko);
                CP_ASYNC16(bst[j] + q * STAGE, bpt[j] + ko);
            }
            CP_COMMIT();
        }

        // compute on buffer p: K = 64 (4 k-steps of 16)
        const uint32_t ab = a_lm + p * STAGE;
        const uint32_t bb = b_lm + p * STAGE;
#pragma unroll
        for (int ks = 0; ks < 4; ks++) {
            uint32_t af0[4], af1[4];
            LDSM_X4(af0, ab + ks * 32);
            LDSM_X4(af1, ab + ks * 32 + 16 * 144);
            uint32_t bf[4][4];
#pragma unroll
            for (int bt = 0; bt < 4; bt++)
                LDSM_X4(bf[bt], bb + ks * 32 + bt * 16 * 144);
#pragma unroll
            for (int nt = 0; nt < 8; nt++) {
                const uint32_t bb0 = (nt & 1) ? bf[nt >> 1][2] : bf[nt >> 1][0];
                const uint32_t bb1 = (nt & 1) ? bf[nt >> 1][3] : bf[nt >> 1][1];
                MMA_BF16(acc[0][nt], af0, bb0, bb1);
                MMA_BF16(acc[1][nt], af1, bb0, bb1);
            }
        }

        if (i < 15) CP_WAIT0();
        __syncthreads();
    }

    const int crow = m_blk + wm * 32 + (lane >> 2);
    const int ccol = n_blk + wn * 64 + ((lane & 3) << 1);
    if (OUTBF) {
        bf16* C = (bf16*)Cv;
#pragma unroll
        for (int mt = 0; mt < 2; mt++)
#pragma unroll
            for (int nt = 0; nt < 8; nt++) {
                bf16* cp = C + (size_t)(crow + mt * 16) * 1024 + ccol + nt * 8;
                *(uint32_t*)cp = packbf(acc[mt][nt][0], acc[mt][nt][1]);
                *(uint32_t*)(cp + 8 * 1024) = packbf(acc[mt][nt][2], acc[mt][nt][3]);
            }
    } else {
        float* C = (float*)Cv;
#pragma unroll
        for (int mt = 0; mt < 2; mt++)
#pragma unroll
            for (int nt = 0; nt < 8; nt++) {
                float* cp = C + (size_t)(crow + mt * 16) * 1024 + ccol + nt * 8;
                *(float2*)cp = make_float2(acc[mt][nt][0], acc[mt][nt][1]);
                *(float2*)(cp + 8 * 1024) = make_float2(acc[mt][nt][2], acc[mt][nt][3]);
            }
    }
}

// ===========================================================================
// Tensor-core flash attention, bf16 in / bf16 out, online softmax (fp32 state).
// Grid (S/64, B*H). 128 threads = 4 warps; warp = 16 q-rows x 128 keys.
// ===========================================================================
__global__ __launch_bounds__(128) void attn_mma(
    const bf16* __restrict__ qp, const bf16* __restrict__ kp,
    const bf16* __restrict__ vp, bf16* __restrict__ out)
{
    __shared__ __align__(16) bf16 Qs[64 * 72];
    __shared__ __align__(16) bf16 Ks[128 * 72];
    __shared__ __align__(16) bf16 Vs[128 * 72];

    const int tid = threadIdx.x, lane = tid & 31, w = tid >> 5;
    const int bh = blockIdx.y, b = bh >> 4, h = bh & 15;
    const int m0 = blockIdx.x << 6;
    const size_t hb = (size_t)b * E_DIM + h * D_HEAD;
    const bf16* qb = qp + hb;
    const bf16* kb = kp + hb;
    const bf16* vb = vp + hb;

    const uint32_t sQ = smem_u32(Qs), sK = smem_u32(Ks), sV = smem_u32(Vs);

#pragma unroll
    for (int j = 0; j < 4; j++) {
        const int c = tid + 128 * j;
        const int rr = c >> 3, sg = (c & 7) << 3;
        CP_ASYNC16(sQ + (uint32_t)(rr * 144 + sg * 2),
                   qb + (size_t)(m0 + rr) * NB + sg);
    }
    CP_COMMIT();

    const uint32_t aQ = sQ + (uint32_t)((w * 16 + (lane & 15)) * 144) + ((lane >> 4) << 4);
    const uint32_t bK = sK + (uint32_t)(((((lane >> 4) & 1) << 3) + (lane & 7)) * 144)
                           + (((lane >> 3) & 1) << 4);
    const uint32_t bV = sV + (uint32_t)(((lane & 7) + (((lane >> 3) & 1) << 3)) * 144)
                           + ((lane >> 4) << 4);

    float m0r = -1e30f, m1r = -1e30f, l0 = 0.f, l1 = 0.f;
    float o[8][4];
#pragma unroll
    for (int nt = 0; nt < 8; nt++)
#pragma unroll
        for (int j = 0; j < 4; j++) o[nt][j] = 0.f;

    for (int t0 = 0; t0 < S_LEN; t0 += 128) {
        __syncthreads();
#pragma unroll
        for (int j = 0; j < 8; j++) {
            const int c = tid + 128 * j;
            const int rr = c >> 3, sg = (c & 7) << 3;
            const uint32_t so = (uint32_t)(rr * 144 + sg * 2);
            const size_t go = (size_t)(t0 + rr) * NB + sg;
            CP_ASYNC16(sK + so, kb + go);
            CP_ASYNC16(sV + so, vb + go);
        }
        CP_COMMIT();
        CP_WAIT0();
        __syncthreads();

        float s[16][4];
#pragma unroll
        for (int nt = 0; nt < 16; nt++)
#pragma unroll
            for (int j = 0; j < 4; j++) s[nt][j] = 0.f;

#pragma unroll
        for (int ks = 0; ks < 4; ks++) {
            uint32_t aq[4];
            LDSM_X4(aq, aQ + ks * 32);
#pragma unroll
            for (int bt = 0; bt < 8; bt++) {
                uint32_t bk[4];
                LDSM_X4(bk, bK + bt * (16 * 144) + ks * 32);
                MMA_BF16(s[2 * bt], aq, bk[0], bk[1]);
                MMA_BF16(s[2 * bt + 1], aq, bk[2], bk[3]);
            }
        }

        float mx0 = m0r, mx1 = m1r;
#pragma unroll
        for (int nt = 0; nt < 16; nt++) {
            s[nt][0] *= 0.125f; s[nt][1] *= 0.125f;
            s[nt][2] *= 0.125f; s[nt][3] *= 0.125f;
            mx0 = fmaxf(mx0, fmaxf(s[nt][0], s[nt][1]));
            mx1 = fmaxf(mx1, fmaxf(s[nt][2], s[nt][3]));
        }
        mx0 = fmaxf(mx0, __shfl_xor_sync(0xffffffffu, mx0, 1, 4));
        mx0 = fmaxf(mx0, __shfl_xor_sync(0xffffffffu, mx0, 2, 4));
        mx1 = fmaxf(mx1, __shfl_xor_sync(0xffffffffu, mx1, 1, 4));
        mx1 = fmaxf(mx1, __shfl_xor_sync(0xffffffffu, mx1, 2, 4));
        const float f0 = __expf(m0r - mx0), f1 = __expf(m1r - mx1);
        float r0 = 0.f, r1 = 0.f;
#pragma unroll
        for (int nt = 0; nt < 16; nt++) {
            s[nt][0] = __expf(s[nt][0] - mx0);
            s[nt][1] = __expf(s[nt][1] - mx0);
            s[nt][2] = __expf(s[nt][2] - mx1);
            s[nt][3] = __expf(s[nt][3] - mx1);
            r0 += s[nt][0] + s[nt][1];
            r1 += s[nt][2] + s[nt][3];
        }
        r0 += __shfl_xor_sync(0xffffffffu, r0, 1, 4);
        r0 += __shfl_xor_sync(0xffffffffu, r0, 2, 4);
        r1 += __shfl_xor_sync(0xffffffffu, r1, 1, 4);
        r1 += __shfl_xor_sync(0xffffffffu, r1, 2, 4);
        l0 = l0 * f0 + r0; l1 = l1 * f1 + r1;
        m0r = mx0; m1r = mx1;
#pragma unroll
        for (int nt = 0; nt < 8; nt++) {
            o[nt][0] *= f0; o[nt][1] *= f0;
            o[nt][2] *= f1; o[nt][3] *= f1;
        }

#pragma unroll
        for (int kk = 0; kk < 8; kk++) {
            uint32_t pa[4];
            pa[0] = packbf(s[2 * kk][0], s[2 * kk][1]);
            pa[1] = packbf(s[2 * kk][2], s[2 * kk][3]);
            pa[2] = packbf(s[2 * kk + 1][0], s[2 * kk + 1][1]);
            pa[3] = packbf(s[2 * kk + 1][2], s[2 * kk + 1][3]);
            const uint32_t vbase = bV + kk * (16 * 144);
#pragma unroll
            for (int vt = 0; vt < 4; vt++) {
                uint32_t bv[4];
                LDSM_X4T(bv, vbase + vt * 32);
                MMA_BF16(o[2 * vt], pa, bv[0], bv[1]);
                MMA_BF16(o[2 * vt + 1], pa, bv[2], bv[3]);
            }
        }
    }

    const int row0 = m0 + w * 16 + (lane >> 2);
    const int col = (lane & 3) << 1;
    const float i0 = 1.f / l0, i1 = 1.f / l1;
    bf16* ob0 = out + (size_t)row0 * NB + hb;
    bf16* ob1 = out + (size_t)(row0 + 8) * NB + hb;
#pragma unroll
    for (int nt = 0; nt < 8; nt++) {
        *(uint32_t*)(ob0 + nt * 8 + col) = packbf(o[nt][0] * i0, o[nt][1] * i0);
        *(uint32_t*)(ob1 + nt * 8 + col) = packbf(o[nt][2] * i1, o[nt][3] * i1);
    }
}

// ===========================================================================
// Weight fp32 -> bf16 convert: 8M elements into g_wbf
// ===========================================================================
__global__ __launch_bounds__(256) void convw_kernel(
    const float* __restrict__ Wq, const float* __restrict__ Wk,
    const float* __restrict__ Wv, const float* __restrict__ inp,
    const float* __restrict__ outp, const float* __restrict__ projw,
    bf16* __restrict__ dst)
{
    const int idx = blockIdx.x * 256 + threadIdx.x;
    const size_t e = (size_t)idx << 2;
    const int seg = (int)(e >> 20);
    const size_t off = e & 0xFFFFFu;
    const float* src;
    switch (seg) {
        case 0: src = Wq; break;
        case 1: src = Wk; break;
        case 2: src = Wv; break;
        case 3: case 4: case 5: src = inp + ((size_t)(seg - 3) << 20); break;
        case 6: src = outp; break;
        default: src = projw; break;
    }
    const float4 v = *(const float4*)(src + off);
    uint2 pv;
    pv.x = packbf(v.x, v.y);
    pv.y = packbf(v.z, v.w);
    *reinterpret_cast<uint2*>(dst + e) = pv;
}

// Input activations fp32 -> bf16: query -> d0, key -> d1, value -> d2 (8M each)
__global__ __launch_bounds__(256) void convin_kernel(
    const float* __restrict__ q, const float* __restrict__ k,
    const float* __restrict__ v,
    bf16* __restrict__ d0, bf16* __restrict__ d1, bf16* __restrict__ d2)
{
    const int idx = blockIdx.x * 256 + threadIdx.x;     // 6M threads
    const size_t e = ((size_t)idx << 2) & (M8 - 1);
    const int seg = idx >> 21;
    const float* src = (seg == 0) ? q : (seg == 1) ? k : v;
    bf16* dst = (seg == 0) ? d0 : (seg == 1) ? d1 : d2;
    const float4 t = *(const float4*)(src + e);
    uint2 pv;
    pv.x = packbf(t.x, t.y);
    pv.y = packbf(t.z, t.w);
    *reinterpret_cast<uint2*>(dst + e) = pv;
}

// ---------------------------------------------------------------------------
// RoPE on bf16, position index = batch b (per reference!). In-place, [S,B,E].
// ---------------------------------------------------------------------------
__global__ __launch_bounds__(256) void rope_kernel(bf16* __restrict__ q,
                                                   bf16* __restrict__ k)
{
    const int idx = blockIdx.x * 256 + threadIdx.x;
    const int j  = idx & 31;
    const int h  = (idx >> 5) & (H_NUM - 1);
    const int sb = idx >> 9;
    const int b  = sb & (B_SZ - 1);
    const size_t base = (size_t)sb * E_DIM + h * D_HEAD;
    const float inv = expf((float)j * (-0.28782313662425575f)); // ln(1e4)/32
    const float ang = (float)b * inv;
    const float c = cosf(ang), s = sinf(ang);
    float x1 = __bfloat162float(q[base + j]);
    float x2 = __bfloat162float(q[base + j + 32]);
    q[base + j]      = __float2bfloat16(x1 * c - x2 * s);
    q[base + j + 32] = __float2bfloat16(x2 * c + x1 * s);
    x1 = __bfloat162float(k[base + j]);
    x2 = __bfloat162float(k[base + j + 32]);
    k[base + j]      = __float2bfloat16(x1 * c - x2 * s);
    k[base + j + 32] = __float2bfloat16(x2 * c + x1 * s);
}

// ---------------------------------------------------------------------------
// x = query + ob ; LayerNorm(last dim) * gamma + beta.
// ---------------------------------------------------------------------------
__global__ __launch_bounds__(256) void addln_kernel(
    const float* __restrict__ qin, const float* __restrict__ ob,
    const float* __restrict__ gamma, const float* __restrict__ beta,
    float* __restrict__ out)
{
    const int row = blockIdx.x;
    const int tid = threadIdx.x;
    const size_t base = (size_t)row * E_DIM;

    const float4 a = *(const float4*)(qin + base + tid*4);
    const float4 c = *(const float4*)(ob  + base + tid*4);
    const float e0 = a.x + c.x, e1 = a.y + c.y, e2 = a.z + c.z, e3 = a.w + c.w;
    float s  = e0 + e1 + e2 + e3;
    float ss = e0*e0 + e1*e1 + e2*e2 + e3*e3;
#pragma unroll
    for (int off = 16; off > 0; off >>= 1) {
        s  += __shfl_xor_sync(0xffffffffu, s,  off);
        ss += __shfl_xor_sync(0xffffffffu, ss, off);
    }
    __shared__ float sw[8], ssw[8], red[2];
    const int wid = tid >> 5, lane = tid & 31;
    if (lane == 0) { sw[wid] = s; ssw[wid] = ss; }
    __syncthreads();
    if (tid == 0) {
        float S2 = 0.f, SS = 0.f;
        for (int i = 0; i < 8; i++) { S2 += sw[i]; SS += ssw[i]; }
        red[0] = S2; red[1] = SS;
    }
    __syncthreads();
    const float mu  = red[0] * (1.0f / E_DIM);
    const float var = red[1] * (1.0f / E_DIM) - mu * mu;
    const float r   = rsqrtf(var + 1e-5f);
    const float4 g  = *(const float4*)(gamma + tid*4);
    const float4 bt = *(const float4*)(beta  + tid*4);
    float4 o;
    o.x = (e0 - mu) * r * g.x + bt.x;
    o.y = (e1 - mu) * r * g.y + bt.y;
    o.z = (e2 - mu) * r * g.z + bt.z;
    o.w = (e3 - mu) * r * g.w + bt.w;
    *(float4*)(out + base + tid*4) = o;
}

// ---------------------------------------------------------------------------
extern "C" void kernel_launch(void* const* d_in, const int* in_sizes, int n_in,
                              void* d_out, int out_size)
{
    const float* query    = (const float*)d_in[0];
    const float* key      = (const float*)d_in[1];
    const float* value    = (const float*)d_in[2];
    const float* Wq       = (const float*)d_in[3];
    const float* Wk       = (const float*)d_in[4];
    const float* Wv       = (const float*)d_in[5];
    const float* in_proj  = (const float*)d_in[6];
    const float* out_proj = (const float*)d_in[7];
    const float* proj     = (const float*)d_in[8];
    const float* gamma    = (const float*)d_in[9];
    const float* beta     = (const float*)d_in[10];
    float* out = (float*)d_out;

    float *pa, *pb, *pc, *pqp, *pkp, *pvp;
    bf16* pwbf;
    cudaGetSymbolAddress((void**)&pa,  g_a);
    cudaGetSymbolAddress((void**)&pb,  g_b);
    cudaGetSymbolAddress((void**)&pc,  g_c);
    cudaGetSymbolAddress((void**)&pqp, g_qp);
    cudaGetSymbolAddress((void**)&pkp, g_kp);
    cudaGetSymbolAddress((void**)&pvp, g_vp);
    cudaGetSymbolAddress((void**)&pwbf, g_wbf);

    // bf16 tensor aliases (two 8M-bf16 tensors per fp32 buffer)
    bf16* bfQin = (bf16*)pa;         bf16* bfKin = (bf16*)pa + M8;
    bf16* bfVin = (bf16*)pb;         bf16* q_bf  = (bf16*)pb + M8;
    bf16* k_bf  = (bf16*)pc;         bf16* v_bf  = (bf16*)pc + M8;
    bf16* qp_b  = (bf16*)pqp;        bf16* kp_b  = (bf16*)pqp + M8;
    bf16* vp_b  = (bf16*)pkp;        bf16* O_bf  = (bf16*)pkp + M8;
    bf16* ob1   = (bf16*)pvp;
    float* obf32 = pa;               // reuses g_a after bfQin/bfKin consumed

    cudaFuncSetAttribute(gemm_bf<true>,
        cudaFuncAttributeMaxDynamicSharedMemorySize, GEMM_SMEM);
    cudaFuncSetAttribute(gemm_bf<false>,
        cudaFuncAttributeMaxDynamicSharedMemorySize, GEMM_SMEM);

    const size_t M1 = 1u << 20;

    // converts
    convw_kernel<<<8192, 256>>>(Wq, Wk, Wv, in_proj, out_proj, proj, pwbf);
    convin_kernel<<<24576, 256>>>(query, key, value, bfQin, bfKin, bfVin);

    const dim3 gg(8, 64);   // N blocks (8 x 128), M blocks (64 x 128)

    // q,k,v = swap(inputs) @ W{q,k,v}.T -> bf16 [S,B,E]
    // A row m=s*B+b at (m%8)*S*E + (m/8)*E
    gemm_bf<true><<<gg, 256, GEMM_SMEM>>>(bfQin, pwbf + 0*M1, q_bf, B_SZ, S_LEN*E_DIM, E_DIM);
    gemm_bf<true><<<gg, 256, GEMM_SMEM>>>(bfKin, pwbf + 1*M1, k_bf, B_SZ, S_LEN*E_DIM, E_DIM);
    gemm_bf<true><<<gg, 256, GEMM_SMEM>>>(bfVin, pwbf + 2*M1, v_bf, B_SZ, S_LEN*E_DIM, E_DIM);

    // RoPE in-place on q_bf, k_bf; position index = b
    rope_kernel<<<(S_LEN * B_SZ * H_NUM * 32) / 256, 256>>>(q_bf, k_bf);

    // in_proj splits -> bf16
    gemm_bf<true><<<gg, 256, GEMM_SMEM>>>(q_bf, pwbf + 3*M1, qp_b, 1, 0, E_DIM);
    gemm_bf<true><<<gg, 256, GEMM_SMEM>>>(k_bf, pwbf + 4*M1, kp_b, 1, 0, E_DIM);
    gemm_bf<true><<<gg, 256, GEMM_SMEM>>>(v_bf, pwbf + 5*M1, vp_b, 1, 0, E_DIM);

    // tensor-core attention -> O_bf [S,B,E]
    const dim3 ga(S_LEN / 64, B_SZ * H_NUM);   // (16, 128)
    attn_mma<<<ga, 128>>>(qp_b, kp_b, vp_b, O_bf);

    // out_proj -> bf16
    gemm_bf<true><<<gg, 256, GEMM_SMEM>>>(O_bf, pwbf + 6*M1, ob1, 1, 0, E_DIM);

    // final proj, [S,B,E]->[B,S,E] gather (row m=b*S+s at s*NB + b*E) -> fp32
    gemm_bf<false><<<gg, 256, GEMM_SMEM>>>(ob1, pwbf + 7*M1, obf32, S_LEN, NB, E_DIM);

    // residual + layernorm -> out [B,S,O]
    addln_kernel<<<B_SZ * S_LEN, 256>>>(query, obf32, gamma, beta, out);
}

// round 10
// speedup vs baseline: 6.9507x; 1.1013x over previous
#include <cuda_runtime.h>
#include <cuda_bf16.h>
#include <cstdint>

#define S_LEN  1024
#define B_SZ   8
#define E_DIM  1024
#define H_NUM  16
#define D_HEAD 64
#define NB     (B_SZ * E_DIM)           /* 8192 = s-stride in [S,B,E] */
#define NBUF   (S_LEN * B_SZ * E_DIM)   /* 8M floats */
#define M8     (1u << 23)               /* 8M elements */

typedef __nv_bfloat16 bf16;

// Scratch (no allocations allowed)
__device__ bf16  g_in[3u * M8];    // bfQin | bfKin | bfVin
__device__ bf16  g_t1[3u * M8];    // q_bf | k_bf | v_bf   (rope fused in GEMM)
__device__ bf16  g_t2[3u * M8];    // qp | kp | vp
__device__ bf16  g_att[M8];        // attention output O
__device__ bf16  g_ob[M8];         // out_proj output
__device__ float g_f[NBUF];        // final proj fp32
__device__ bf16  g_wbf[8u * 1024u * 1024u];   // bf16 weights, 8 x 1M

// ===========================================================================
// Family-portable PTX helpers (NO tcgen05 — harness compiles compute_103)
// ===========================================================================
__device__ __forceinline__ uint32_t smem_u32(const void* p) {
    uint32_t a;
    asm("{ .reg .u64 t; cvta.to.shared.u64 t, %1; cvt.u32.u64 %0, t; }"
        : "=r"(a) : "l"(p));
    return a;
}

#define LDSM_X4(d, addr)                                                        \
    asm volatile("ldmatrix.sync.aligned.m8n8.x4.shared.b16 {%0,%1,%2,%3}, [%4];"\
        : "=r"((d)[0]), "=r"((d)[1]), "=r"((d)[2]), "=r"((d)[3]) : "r"(addr))

#define LDSM_X4T(d, addr)                                                       \
    asm volatile("ldmatrix.sync.aligned.m8n8.x4.trans.shared.b16 {%0,%1,%2,%3}, [%4];"\
        : "=r"((d)[0]), "=r"((d)[1]), "=r"((d)[2]), "=r"((d)[3]) : "r"(addr))

#define MMA_BF16(ac, a, b0, b1)                                                 \
    asm volatile("mma.sync.aligned.m16n8k16.row.col.f32.bf16.bf16.f32 "         \
        "{%0,%1,%2,%3}, {%4,%5,%6,%7}, {%8,%9}, {%0,%1,%2,%3};"                 \
        : "+f"((ac)[0]), "+f"((ac)[1]), "+f"((ac)[2]), "+f"((ac)[3])            \
        : "r"((a)[0]), "r"((a)[1]), "r"((a)[2]), "r"((a)[3]),                   \
          "r"(b0), "r"(b1))

#define CP_ASYNC16(s, g)                                                        \
    asm volatile("cp.async.cg.shared.global [%0], [%1], 16;" :: "r"(s), "l"(g))
#define CP_COMMIT() asm volatile("cp.async.commit_group;" ::: "memory")
#define CP_WAIT0()  asm volatile("cp.async.wait_group 0;" ::: "memory")
#define CP_WAIT1()  asm volatile("cp.async.wait_group 1;" ::: "memory")

__device__ __forceinline__ uint32_t packbf(float x, float y) {
    __nv_bfloat162 t = __floats2bfloat162_rn(x, y);
    return *reinterpret_cast<uint32_t*>(&t);
}

// ===========================================================================
// All-bf16 mma.sync GEMM, 3-stage cp.async pipeline.
// C[m, n] = sum_k A_row(m)[k] * Bw[n*1024 + k]; M=8192, N=1024, K=1024.
// CTA 128x128, K-chunk 64, 8 warps (4m x 2n), warp tile 32x64.
// Padded rows: 72 bf16 = 144 B. A row m at A + (m%P)*sa0 + (m/P)*sa1.
// grid.z batches GEMMs: A += z*zA, Bw += z*1M, C += z*zC (bf16 path).
// rope_z: blocks with z < rope_z apply RoPE (pos = row%8) in epilogue.
// ===========================================================================
#define GTB   (128 * 72 * 2)     /* 18432 B per tile */
#define STAGE (2 * GTB)          /* 36864 B per stage (A + B) */
#define GEMM_SMEM (3 * STAGE)    /* 110592 B */

template<bool OUTBF>
__global__ __launch_bounds__(256, 2) void gemm_bf(
    const bf16* __restrict__ A0, const bf16* __restrict__ W0,
    void* __restrict__ Cv, int P, int sa0, int sa1,
    int zA, int zC, int rope_z)
{
    extern __shared__ __align__(16) char smp[];
    const uint32_t s0 = smem_u32(smp);

    const int z = blockIdx.z;
    const bf16* A  = A0 + (size_t)z * (uint32_t)zA;
    const bf16* Bw = W0 + ((size_t)z << 20);

    const int tid  = threadIdx.x;
    const int lane = tid & 31;
    const int w    = tid >> 5;
    const int wm   = w >> 1;          // 0..3
    const int wn   = w & 1;           // 0..1
    const int m_blk = blockIdx.y << 7;
    const int n_blk = blockIdx.x << 7;

    // 1024 chunks (8 bf16 each) per tile / 256 threads = 4 per thread
    const bf16* apt[4];
    const bf16* bpt[4];
    uint32_t ast[4], bst[4];
#pragma unroll
    for (int j = 0; j < 4; j++) {
        const int c = tid + 256 * j;
        const int row = c >> 3, sg = (c & 7) << 3;
        const int m = m_blk + row;
        apt[j] = A + (size_t)(m % P) * sa0 + (size_t)(m / P) * sa1 + sg;
        bpt[j] = Bw + (size_t)(n_blk + row) * 1024 + sg;
        ast[j] = s0 + (uint32_t)(row * 144 + sg * 2);
        bst[j] = s0 + GTB + (uint32_t)(row * 144 + sg * 2);
    }

    const uint32_t a_lm = s0 +
        (uint32_t)((wm * 32 + (lane & 15)) * 144) + ((lane >> 4) << 4);
    const uint32_t b_lm = s0 + GTB +
        (uint32_t)((wn * 64 + (((lane >> 4) & 1) << 3) + (lane & 7)) * 144)
        + (((lane >> 3) & 1) << 4);

    float acc[2][8][4];
#pragma unroll
    for (int mt = 0; mt < 2; mt++)
#pragma unroll
        for (int nt = 0; nt < 8; nt++)
#pragma unroll
            for (int j = 0; j < 4; j++) acc[mt][nt][j] = 0.f;

    // prologue: stages 0 and 1
#pragma unroll
    for (int j = 0; j < 4; j++) {
        CP_ASYNC16(ast[j], apt[j]);
        CP_ASYNC16(bst[j], bpt[j]);
    }
    CP_COMMIT();
#pragma unroll
    for (int j = 0; j < 4; j++) {
        CP_ASYNC16(ast[j] + STAGE, apt[j] + 64);
        CP_ASYNC16(bst[j] + STAGE, bpt[j] + 64);
    }
    CP_COMMIT();
    CP_WAIT1();
    __syncthreads();

    uint32_t cb = 0, lb = 2;
    for (int i = 0; i < 16; i++) {
        if (i < 14) {
            const int ko = (i + 2) << 6;
            const uint32_t lo = lb * STAGE;
#pragma unroll
            for (int j = 0; j < 4; j++) {
                CP_ASYNC16(ast[j] + lo, apt[j] + ko);
                CP_ASYNC16(bst[j] + lo, bpt[j] + ko);
            }
            CP_COMMIT();
        }

        const uint32_t co = cb * STAGE;
        const uint32_t ab = a_lm + co;
        const uint32_t bb = b_lm + co;
#pragma unroll
        for (int ks = 0; ks < 4; ks++) {
            uint32_t af0[4], af1[4];
            LDSM_X4(af0, ab + ks * 32);
            LDSM_X4(af1, ab + ks * 32 + 16 * 144);
            uint32_t bfr[4][4];
#pragma unroll
            for (int bt = 0; bt < 4; bt++)
                LDSM_X4(bfr[bt], bb + ks * 32 + bt * 16 * 144);
#pragma unroll
            for (int nt = 0; nt < 8; nt++) {
                const uint32_t bb0 = (nt & 1) ? bfr[nt >> 1][2] : bfr[nt >> 1][0];
                const uint32_t bb1 = (nt & 1) ? bfr[nt >> 1][3] : bfr[nt >> 1][1];
                MMA_BF16(acc[0][nt], af0, bb0, bb1);
                MMA_BF16(acc[1][nt], af1, bb0, bb1);
            }
        }

        if (i < 14)      CP_WAIT1();
        else if (i == 14) CP_WAIT0();
        __syncthreads();
        cb = (cb == 2) ? 0 : cb + 1;
        lb = (lb == 2) ? 0 : lb + 1;
    }

    const int crow = m_blk + wm * 32 + (lane >> 2);
    const int ccol = n_blk + wn * 64 + ((lane & 3) << 1);

    // Fused RoPE (position index = b = row % 8; head-local pair (j, j+32) =
    // (nt, nt+4) in the same thread; b identical for rows crow, +8, +16, +24)
    if (OUTBF && z < rope_z) {
        const float bpos = (float)(crow & 7);
        float cs[8], sn[8];
#pragma unroll
        for (int nt = 0; nt < 4; nt++)
#pragma unroll
            for (int c1 = 0; c1 < 2; c1++) {
                const int j = nt * 8 + ((lane & 3) << 1) + c1;
                const float invf = __expf(-0.28782313662425575f * (float)j);
                __sincosf(bpos * invf, &sn[nt * 2 + c1], &cs[nt * 2 + c1]);
            }
#pragma unroll
        for (int mt = 0; mt < 2; mt++)
#pragma unroll
            for (int nt = 0; nt < 4; nt++)
#pragma unroll
                for (int c = 0; c < 4; c++) {
                    const int a = nt * 2 + (c & 1);
                    const float x1 = acc[mt][nt][c], x2 = acc[mt][nt + 4][c];
                    acc[mt][nt][c]     = x1 * cs[a] - x2 * sn[a];
                    acc[mt][nt + 4][c] = x2 * cs[a] + x1 * sn[a];
                }
    }

    if (OUTBF) {
        bf16* C = (bf16*)Cv + (size_t)z * (uint32_t)zC;
#pragma unroll
        for (int mt = 0; mt < 2; mt++)
#pragma unroll
            for (int nt = 0; nt < 8; nt++) {
                bf16* cp = C + (size_t)(crow + mt * 16) * 1024 + ccol + nt * 8;
                *(uint32_t*)cp = packbf(acc[mt][nt][0], acc[mt][nt][1]);
                *(uint32_t*)(cp + 8 * 1024) = packbf(acc[mt][nt][2], acc[mt][nt][3]);
            }
    } else {
        float* C = (float*)Cv;
#pragma unroll
        for (int mt = 0; mt < 2; mt++)
#pragma unroll
            for (int nt = 0; nt < 8; nt++) {
                float* cp = C + (size_t)(crow + mt * 16) * 1024 + ccol + nt * 8;
                *(float2*)cp = make_float2(acc[mt][nt][0], acc[mt][nt][1]);
                *(float2*)(cp + 8 * 1024) = make_float2(acc[mt][nt][2], acc[mt][nt][3]);
            }
    }
}

// ===========================================================================
// Tensor-core flash attention, bf16 in / bf16 out, online softmax (fp32 state).
// Grid (S/64, B*H). 128 threads = 4 warps; warp = 16 q-rows x 128 keys.
// ===========================================================================
__global__ __launch_bounds__(128) void attn_mma(
    const bf16* __restrict__ qp, const bf16* __restrict__ kp,
    const bf16* __restrict__ vp, bf16* __restrict__ out)
{
    __shared__ __align__(16) bf16 Qs[64 * 72];
    __shared__ __align__(16) bf16 Ks[128 * 72];
    __shared__ __align__(16) bf16 Vs[128 * 72];

    const int tid = threadIdx.x, lane = tid & 31, w = tid >> 5;
    const int bh = blockIdx.y, b = bh >> 4, h = bh & 15;
    const int m0 = blockIdx.x << 6;
    const size_t hb = (size_t)b * E_DIM + h * D_HEAD;
    const bf16* qb = qp + hb;
    const bf16* kb = kp + hb;
    const bf16* vb = vp + hb;

    const uint32_t sQ = smem_u32(Qs), sK = smem_u32(Ks), sV = smem_u32(Vs);

#pragma unroll
    for (int j = 0; j < 4; j++) {
        const int c = tid + 128 * j;
        const int rr = c >> 3, sg = (c & 7) << 3;
        CP_ASYNC16(sQ + (uint32_t)(rr * 144 + sg * 2),
                   qb + (size_t)(m0 + rr) * NB + sg);
    }
    CP_COMMIT();

    const uint32_t aQ = sQ + (uint32_t)((w * 16 + (lane & 15)) * 144) + ((lane >> 4) << 4);
    const uint32_t bK = sK + (uint32_t)(((((lane >> 4) & 1) << 3) + (lane & 7)) * 144)
                           + (((lane >> 3) & 1) << 4);
    const uint32_t bV = sV + (uint32_t)(((lane & 7) + (((lane >> 3) & 1) << 3)) * 144)
                           + ((lane >> 4) << 4);

    float m0r = -1e30f, m1r = -1e30f, l0 = 0.f, l1 = 0.f;
    float o[8][4];
#pragma unroll
    for (int nt = 0; nt < 8; nt++)
#pragma unroll
        for (int j = 0; j < 4; j++) o[nt][j] = 0.f;

    for (int t0 = 0; t0 < S_LEN; t0 += 128) {
        __syncthreads();
#pragma unroll
        for (int j = 0; j < 8; j++) {
            const int c = tid + 128 * j;
            const int rr = c >> 3, sg = (c & 7) << 3;
            const uint32_t so = (uint32_t)(rr * 144 + sg * 2);
            const size_t go = (size_t)(t0 + rr) * NB + sg;
            CP_ASYNC16(sK + so, kb + go);
            CP_ASYNC16(sV + so, vb + go);
        }
        CP_COMMIT();
        CP_WAIT0();
        __syncthreads();

        float s[16][4];
#pragma unroll
        for (int nt = 0; nt < 16; nt++)
#pragma unroll
            for (int j = 0; j < 4; j++) s[nt][j] = 0.f;

#pragma unroll
        for (int ks = 0; ks < 4; ks++) {
            uint32_t aq[4];
            LDSM_X4(aq, aQ + ks * 32);
#pragma unroll
            for (int bt = 0; bt < 8; bt++) {
                uint32_t bk[4];
                LDSM_X4(bk, bK + bt * (16 * 144) + ks * 32);
                MMA_BF16(s[2 * bt], aq, bk[0], bk[1]);
                MMA_BF16(s[2 * bt + 1], aq, bk[2], bk[3]);
            }
        }

        float mx0 = m0r, mx1 = m1r;
#pragma unroll
        for (int nt = 0; nt < 16; nt++) {
            s[nt][0] *= 0.125f; s[nt][1] *= 0.125f;
            s[nt][2] *= 0.125f; s[nt][3] *= 0.125f;
            mx0 = fmaxf(mx0, fmaxf(s[nt][0], s[nt][1]));
            mx1 = fmaxf(mx1, fmaxf(s[nt][2], s[nt][3]));
        }
        mx0 = fmaxf(mx0, __shfl_xor_sync(0xffffffffu, mx0, 1, 4));
        mx0 = fmaxf(mx0, __shfl_xor_sync(0xffffffffu, mx0, 2, 4));
        mx1 = fmaxf(mx1, __shfl_xor_sync(0xffffffffu, mx1, 1, 4));
        mx1 = fmaxf(mx1, __shfl_xor_sync(0xffffffffu, mx1, 2, 4));
        const float f0 = __expf(m0r - mx0), f1 = __expf(m1r - mx1);
        float r0 = 0.f, r1 = 0.f;
#pragma unroll
        for (int nt = 0; nt < 16; nt++) {
            s[nt][0] = __expf(s[nt][0] - mx0);
            s[nt][1] = __expf(s[nt][1] - mx0);
            s[nt][2] = __expf(s[nt][2] - mx1);
            s[nt][3] = __expf(s[nt][3] - mx1);
            r0 += s[nt][0] + s[nt][1];
            r1 += s[nt][2] + s[nt][3];
        }
        r0 += __shfl_xor_sync(0xffffffffu, r0, 1, 4);
        r0 += __shfl_xor_sync(0xffffffffu, r0, 2, 4);
        r1 += __shfl_xor_sync(0xffffffffu, r1, 1, 4);
        r1 += __shfl_xor_sync(0xffffffffu, r1, 2, 4);
        l0 = l0 * f0 + r0; l1 = l1 * f1 + r1;
        m0r = mx0; m1r = mx1;
#pragma unroll
        for (int nt = 0; nt < 8; nt++) {
            o[nt][0] *= f0; o[nt][1] *= f0;
            o[nt][2] *= f1; o[nt][3] *= f1;
        }

#pragma unroll
        for (int kk = 0; kk < 8; kk++) {
            uint32_t pa[4];
            pa[0] = packbf(s[2 * kk][0], s[2 * kk][1]);
            pa[1] = packbf(s[2 * kk][2], s[2 * kk][3]);
            pa[2] = packbf(s[2 * kk + 1][0], s[2 * kk + 1][1]);
            pa[3] = packbf(s[2 * kk + 1][2], s[2 * kk + 1][3]);
            const uint32_t vbase = bV + kk * (16 * 144);
#pragma unroll
            for (int vt = 0; vt < 4; vt++) {
                uint32_t bv[4];
                LDSM_X4T(bv, vbase + vt * 32);
                MMA_BF16(o[2 * vt], pa, bv[0], bv[1]);
                MMA_BF16(o[2 * vt + 1], pa, bv[2], bv[3]);
            }
        }
    }

    const int row0 = m0 + w * 16 + (lane >> 2);
    const int col = (lane & 3) << 1;
    const float i0 = 1.f / l0, i1 = 1.f / l1;
    bf16* ob0 = out + (size_t)row0 * NB + hb;
    bf16* ob1 = out + (size_t)(row0 + 8) * NB + hb;
#pragma unroll
    for (int nt = 0; nt < 8; nt++) {
        *(uint32_t*)(ob0 + nt * 8 + col) = packbf(o[nt][0] * i0, o[nt][1] * i0);
        *(uint32_t*)(ob1 + nt * 8 + col) = packbf(o[nt][2] * i1, o[nt][3] * i1);
    }
}

// ===========================================================================
// Weight fp32 -> bf16 convert: 8M elements into g_wbf
// ===========================================================================
__global__ __launch_bounds__(256) void convw_kernel(
    const float* __restrict__ Wq, const float* __restrict__ Wk,
    const float* __restrict__ Wv, const float* __restrict__ inp,
    const float* __restrict__ outp, const float* __restrict__ projw,
    bf16* __restrict__ dst)
{
    const int idx = blockIdx.x * 256 + threadIdx.x;
    const size_t e = (size_t)idx << 2;
    const int seg = (int)(e >> 20);
    const size_t off = e & 0xFFFFFu;
    const float* src;
    switch (seg) {
        case 0: src = Wq; break;
        case 1: src = Wk; break;
        case 2: src = Wv; break;
        case 3: case 4: case 5: src = inp + ((size_t)(seg - 3) << 20); break;
        case 6: src = outp; break;
        default: src = projw; break;
    }
    const float4 v = *(const float4*)(src + off);
    uint2 pv;
    pv.x = packbf(v.x, v.y);
    pv.y = packbf(v.z, v.w);
    *reinterpret_cast<uint2*>(dst + e) = pv;
}

// Input activations fp32 -> bf16: [query | key | value] -> g_in (24M)
__global__ __launch_bounds__(256) void convin_kernel(
    const float* __restrict__ q, const float* __restrict__ k,
    const float* __restrict__ v, bf16* __restrict__ dst)
{
    const int idx = blockIdx.x * 256 + threadIdx.x;     // 6M threads
    const size_t e = (size_t)idx << 2;
    const int seg = (int)(e >> 23);
    const size_t off = e & (M8 - 1);
    const float* src = (seg == 0) ? q : (seg == 1) ? k : v;
    const float4 t = *(const float4*)(src + off);
    uint2 pv;
    pv.x = packbf(t.x, t.y);
    pv.y = packbf(t.z, t.w);
    *reinterpret_cast<uint2*>(dst + e) = pv;
}

// ---------------------------------------------------------------------------
// x = query + ob ; LayerNorm(last dim) * gamma + beta.
// ---------------------------------------------------------------------------
__global__ __launch_bounds__(256) void addln_kernel(
    const float* __restrict__ qin, const float* __restrict__ ob,
    const float* __restrict__ gamma, const float* __restrict__ beta,
    float* __restrict__ out)
{
    const int row = blockIdx.x;
    const int tid = threadIdx.x;
    const size_t base = (size_t)row * E_DIM;

    const float4 a = *(const float4*)(qin + base + tid*4);
    const float4 c = *(const float4*)(ob  + base + tid*4);
    const float e0 = a.x + c.x, e1 = a.y + c.y, e2 = a.z + c.z, e3 = a.w + c.w;
    float s  = e0 + e1 + e2 + e3;
    float ss = e0*e0 + e1*e1 + e2*e2 + e3*e3;
#pragma unroll
    for (int off = 16; off > 0; off >>= 1) {
        s  += __shfl_xor_sync(0xffffffffu, s,  off);
        ss += __shfl_xor_sync(0xffffffffu, ss, off);
    }
    __shared__ float sw[8], ssw[8], red[2];
    const int wid = tid >> 5, lane = tid & 31;
    if (lane == 0) { sw[wid] = s; ssw[wid] = ss; }
    __syncthreads();
    if (tid == 0) {
        float S2 = 0.f, SS = 0.f;
        for (int i = 0; i < 8; i++) { S2 += sw[i]; SS += ssw[i]; }
        red[0] = S2; red[1] = SS;
    }
    __syncthreads();
    const float mu  = red[0] * (1.0f / E_DIM);
    const float var = red[1] * (1.0f / E_DIM) - mu * mu;
    const float r   = rsqrtf(var + 1e-5f);
    const float4 g  = *(const float4*)(gamma + tid*4);
    const float4 bt = *(const float4*)(beta  + tid*4);
    float4 o;
    o.x = (e0 - mu) * r * g.x + bt.x;
    o.y = (e1 - mu) * r * g.y + bt.y;
    o.z = (e2 - mu) * r * g.z + bt.z;
    o.w = (e3 - mu) * r * g.w + bt.w;
    *(float4*)(out + base + tid*4) = o;
}

// ---------------------------------------------------------------------------
extern "C" void kernel_launch(void* const* d_in, const int* in_sizes, int n_in,
                              void* d_out, int out_size)
{
    const float* query    = (const float*)d_in[0];
    const float* key      = (const float*)d_in[1];
    const float* value    = (const float*)d_in[2];
    const float* Wq       = (const float*)d_in[3];
    const float* Wk       = (const float*)d_in[4];
    const float* Wv       = (const float*)d_in[5];
    const float* in_proj  = (const float*)d_in[6];
    const float* out_proj = (const float*)d_in[7];
    const float* proj     = (const float*)d_in[8];
    const float* gamma    = (const float*)d_in[9];
    const float* beta     = (const float*)d_in[10];
    float* out = (float*)d_out;

    bf16 *pin, *pt1, *pt2, *patt, *pob, *pwbf;
    float *pf;
    cudaGetSymbolAddress((void**)&pin,  g_in);
    cudaGetSymbolAddress((void**)&pt1,  g_t1);
    cudaGetSymbolAddress((void**)&pt2,  g_t2);
    cudaGetSymbolAddress((void**)&patt, g_att);
    cudaGetSymbolAddress((void**)&pob,  g_ob);
    cudaGetSymbolAddress((void**)&pf,   g_f);
    cudaGetSymbolAddress((void**)&pwbf, g_wbf);

    cudaFuncSetAttribute(gemm_bf<true>,
        cudaFuncAttributeMaxDynamicSharedMemorySize, GEMM_SMEM);
    cudaFuncSetAttribute(gemm_bf<false>,
        cudaFuncAttributeMaxDynamicSharedMemorySize, GEMM_SMEM);

    const size_t M1 = 1u << 20;

    // converts
    convw_kernel<<<8192, 256>>>(Wq, Wk, Wv, in_proj, out_proj, proj, pwbf);
    convin_kernel<<<24576, 256>>>(query, key, value, pin);

    // trio 1: q,k,v = swap(inputs) @ W{q,k,v}.T -> g_t1, RoPE fused for z<2
    // A row m=s*B+b at (m%8)*S*E + (m/8)*E
    const dim3 g3(8, 64, 3);
    gemm_bf<true><<<g3, 256, GEMM_SMEM>>>(pin, pwbf, pt1,
        B_SZ, S_LEN * E_DIM, E_DIM, (int)M8, (int)M8, 2);

    // trio 2: in_proj splits -> g_t2
    gemm_bf<true><<<g3, 256, GEMM_SMEM>>>(pt1, pwbf + 3 * M1, pt2,
        1, 0, E_DIM, (int)M8, (int)M8, 0);

    // tensor-core attention -> g_att [S,B,E]
    const dim3 ga(S_LEN / 64, B_SZ * H_NUM);   // (16, 128)
    attn_mma<<<ga, 128>>>(pt2, pt2 + M8, pt2 + 2 * M8, patt);

    // out_proj -> g_ob
    const dim3 gg(8, 64, 1);
    gemm_bf<true><<<gg, 256, GEMM_SMEM>>>(patt, pwbf + 6 * M1, pob,
        1, 0, E_DIM, 0, 0, 0);

    // final proj, [S,B,E]->[B,S,E] gather (row m=b*S+s at s*NB + b*E) -> fp32
    gemm_bf<false><<<gg, 256, GEMM_SMEM>>>(pob, pwbf + 7 * M1, pf,
        S_LEN, NB, E_DIM, 0, 0, 0);

    // residual + layernorm -> out [B,S,O]
    addln_kernel<<<B_SZ * S_LEN, 256>>>(query, pf, gamma, beta, out);
}